// round 3
// baseline (speedup 1.0000x reference)
#include <cuda_runtime.h>
#include <math.h>

#define BATCH 4
#define SEQ   1024
#define EMB   512
#define HEADS 8
#define HD    64
#define TOK   (BATCH*SEQ)     // 4096

// Scratch (device globals; no allocations allowed)
__device__ float g_Q [TOK*EMB];
__device__ float g_K [TOK*EMB];
__device__ float g_V [TOK*EMB];
__device__ float g_QG[TOK*EMB];

// ---------------------------------------------------------------------------
// Kernel 1: QKV projections.  C = X @ W + b.  X:[4096,512] W:[512,512]
// blockIdx.z selects q/k/v. 64x64 tile, BK=16, 256 threads, 4x4 microtile.
// ---------------------------------------------------------------------------
__global__ __launch_bounds__(256) void qkv_kernel(
    const float* __restrict__ x,
    const float* __restrict__ Wq, const float* __restrict__ bq,
    const float* __restrict__ Wk, const float* __restrict__ bk,
    const float* __restrict__ Wv, const float* __restrict__ bv)
{
    const int which = blockIdx.z;
    const float* Wm = (which == 0) ? Wq : (which == 1) ? Wk : Wv;
    const float* bm = (which == 0) ? bq : (which == 1) ? bk : bv;
    float* outp     = (which == 0) ? g_Q : (which == 1) ? g_K : g_V;

    __shared__ float As[64 * 20];   // row pad 20 (16B-aligned rows)
    __shared__ float Bs[16 * 68];   // row pad 68

    const int tid = threadIdx.x;
    const int tx  = tid & 15;       // output col group
    const int ty  = tid >> 4;       // output row group
    const int m0  = blockIdx.x * 64;
    const int n0  = blockIdx.y * 64;

    float acc[4][4] = {};

    for (int k0 = 0; k0 < EMB; k0 += 16) {
        __syncthreads();
        {   // load A tile 64x16
            int t  = tid >> 2;
            int c4 = (tid & 3) << 2;
            float4 v = *(const float4*)&x[(size_t)(m0 + t) * EMB + k0 + c4];
            *(float4*)&As[t * 20 + c4] = v;
            // load B tile 16x64
            int r  = tid >> 4;
            int cc = (tid & 15) << 2;
            float4 w = *(const float4*)&Wm[(size_t)(k0 + r) * EMB + n0 + cc];
            *(float4*)&Bs[r * 68 + cc] = w;
        }
        __syncthreads();
        #pragma unroll
        for (int kk = 0; kk < 16; kk++) {
            float4 w = *(const float4*)&Bs[kk * 68 + tx * 4];
            #pragma unroll
            for (int i = 0; i < 4; i++) {
                float a = As[(ty * 4 + i) * 20 + kk];
                acc[i][0] = fmaf(a, w.x, acc[i][0]);
                acc[i][1] = fmaf(a, w.y, acc[i][1]);
                acc[i][2] = fmaf(a, w.z, acc[i][2]);
                acc[i][3] = fmaf(a, w.w, acc[i][3]);
            }
        }
    }

    const float4 bb = *(const float4*)&bm[n0 + tx * 4];
    #pragma unroll
    for (int i = 0; i < 4; i++) {
        float4 o = make_float4(acc[i][0] + bb.x, acc[i][1] + bb.y,
                               acc[i][2] + bb.z, acc[i][3] + bb.w);
        *(float4*)&outp[(size_t)(m0 + ty * 4 + i) * EMB + n0 + tx * 4] = o;
    }
}

// ---------------------------------------------------------------------------
// Kernel 2 (dominant): fused  g = gelu(x@Wg+bg),  qg[t,h,e] = sum_d q[t,h,d]*g[d,e]
// One CTA: 64 tokens x 1 head. Loops d=0..63; per d computes the 64x64 tile of
// x@Wg for columns [h*4096 + d*64, +64), GELUs it, and accumulates into the
// persistent qg register tile. Wg chunks double-buffered via cp.async.
// ---------------------------------------------------------------------------
#define TB   64
#define XS   516   // X row pad
#define QSD  68    // Q row pad
#define WS   68    // Wg chunk row pad
#define BK   16

__global__ __launch_bounds__(256) void qg_kernel(
    const float* __restrict__ x,
    const float* __restrict__ Wg,
    const float* __restrict__ bg)
{
    extern __shared__ float sm[];
    float* Xs  = sm;                 // 64*516
    float* Qs  = Xs + 64 * XS;       // 64*68
    float* bgs = Qs + 64 * QSD;      // 4096
    float* Wgs = bgs + 4096;         // 2*16*68

    const int h    = blockIdx.y;
    const int tok0 = blockIdx.x * TB;
    const int tid  = threadIdx.x;
    const int tx   = tid & 15;
    const int ty   = tid >> 4;

    // Load X tile (64x512)
    #pragma unroll
    for (int it = 0; it < 32; it++) {
        int idx = tid + it * 256;          // float4 index, 0..8191
        int t   = idx >> 7;
        int c4  = (idx & 127) << 2;
        float4 v = *(const float4*)&x[(size_t)(tok0 + t) * EMB + c4];
        *(float4*)&Xs[t * XS + c4] = v;
    }
    // Load Q tile (64x64) for this head
    #pragma unroll
    for (int it = 0; it < 4; it++) {
        int idx = tid + it * 256;          // 0..1023
        int t   = idx >> 4;
        int c4  = (idx & 15) << 2;
        float4 v = *(const float4*)&g_Q[(size_t)(tok0 + t) * EMB + h * 64 + c4];
        *(float4*)&Qs[t * QSD + c4] = v;
    }
    // Load bg slice for this head (4096 floats)
    #pragma unroll
    for (int it = 0; it < 4; it++) {
        int idx = (tid + it * 256) << 2;
        float4 v = *(const float4*)&bg[(size_t)h * 4096 + idx];
        *(float4*)&bgs[idx] = v;
    }
    __syncthreads();

    float qg[4][4] = {};
    const int wrow = tid >> 4;             // 0..15 (k row within chunk)
    const int wc4  = (tid & 15) << 2;      // col within 64

    for (int d = 0; d < 64; d++) {
        float S[4][4] = {};
        const size_t cb = (size_t)h * 4096 + d * 64;   // column base in Wg

        // prologue: chunk 0 -> buf 0
        {
            unsigned dst = (unsigned)__cvta_generic_to_shared(&Wgs[wrow * WS + wc4]);
            const float* src = &Wg[(size_t)wrow * 32768 + cb + wc4];
            asm volatile("cp.async.cg.shared.global [%0], [%1], 16;\n" :: "r"(dst), "l"(src));
            asm volatile("cp.async.commit_group;\n");
        }
        int buf = 0;
        for (int c = 0; c < 32; c++) {
            asm volatile("cp.async.wait_group 0;\n");
            __syncthreads();
            if (c < 31) {
                int nb = buf ^ 1;
                unsigned dst = (unsigned)__cvta_generic_to_shared(
                    &Wgs[nb * (BK * WS) + wrow * WS + wc4]);
                const float* src = &Wg[(size_t)((c + 1) * BK + wrow) * 32768 + cb + wc4];
                asm volatile("cp.async.cg.shared.global [%0], [%1], 16;\n" :: "r"(dst), "l"(src));
                asm volatile("cp.async.commit_group;\n");
            }
            const float* Wb = &Wgs[buf * (BK * WS)];
            const int kbase = c * BK;
            #pragma unroll
            for (int kk4 = 0; kk4 < 4; kk4++) {
                float4 xr[4];
                #pragma unroll
                for (int i = 0; i < 4; i++)
                    xr[i] = *(const float4*)&Xs[(ty * 4 + i) * XS + kbase + kk4 * 4];
                #pragma unroll
                for (int kk = 0; kk < 4; kk++) {
                    float4 w = *(const float4*)&Wb[(kk4 * 4 + kk) * WS + tx * 4];
                    #pragma unroll
                    for (int i = 0; i < 4; i++) {
                        float xv = (&xr[i].x)[kk];
                        S[i][0] = fmaf(xv, w.x, S[i][0]);
                        S[i][1] = fmaf(xv, w.y, S[i][1]);
                        S[i][2] = fmaf(xv, w.z, S[i][2]);
                        S[i][3] = fmaf(xv, w.w, S[i][3]);
                    }
                }
            }
            buf ^= 1;
        }

        // epilogue: gelu + contraction with q[:,h,d]
        #pragma unroll
        for (int i = 0; i < 4; i++) {
            float qv = Qs[(ty * 4 + i) * QSD + d];
            #pragma unroll
            for (int j = 0; j < 4; j++) {
                float s = S[i][j] + bgs[d * 64 + tx * 4 + j];
                float g = 0.5f * s * (1.0f + erff(s * 0.70710678118654752f));
                qg[i][j] = fmaf(qv, g, qg[i][j]);
            }
        }
    }

    #pragma unroll
    for (int i = 0; i < 4; i++) {
        float4 v = make_float4(qg[i][0], qg[i][1], qg[i][2], qg[i][3]);
        *(float4*)&g_QG[(size_t)(tok0 + ty * 4 + i) * EMB + h * 64 + tx * 4] = v;
    }
}

// ---------------------------------------------------------------------------
// Kernel 3: flash-style attention.  scores = QG @ K^T (no 1/sqrt(d) scale),
// softmax over keys, out = P @ V.  One thread = one (b,h,query).
// ---------------------------------------------------------------------------
__global__ __launch_bounds__(128) void attn_kernel(float* __restrict__ out)
{
    __shared__ float Ks[64 * 68];
    __shared__ float Vs[64 * 68];

    const int bh  = blockIdx.y;
    const int b   = bh >> 3;
    const int h   = bh & 7;
    const int tid = threadIdx.x;
    const int n   = blockIdx.x * 128 + tid;
    const size_t rowq = (size_t)(b * SEQ + n) * EMB + h * 64;

    float4 qgr[16], outr[16];
    #pragma unroll
    for (int i = 0; i < 16; i++) {
        qgr[i]  = *(const float4*)&g_QG[rowq + i * 4];
        outr[i] = make_float4(0.f, 0.f, 0.f, 0.f);
    }
    float m = -INFINITY, l = 0.f;

    for (int kb = 0; kb < 16; kb++) {
        __syncthreads();
        #pragma unroll
        for (int it = 0; it < 8; it++) {
            int idx = tid + it * 128;           // 0..1023 float4s
            int r   = idx >> 4;
            int c4  = (idx & 15) << 2;
            size_t g = (size_t)(b * SEQ + kb * 64 + r) * EMB + h * 64 + c4;
            *(float4*)&Ks[r * 68 + c4] = *(const float4*)&g_K[g];
            *(float4*)&Vs[r * 68 + c4] = *(const float4*)&g_V[g];
        }
        __syncthreads();

        #pragma unroll 1
        for (int j0 = 0; j0 < 64; j0 += 8) {
            float s[8];
            #pragma unroll
            for (int jj = 0; jj < 8; jj++) {
                const float* kr = &Ks[(j0 + jj) * 68];
                float a = 0.f;
                #pragma unroll
                for (int e = 0; e < 16; e++) {
                    float4 kv = *(const float4*)&kr[e * 4];
                    a = fmaf(qgr[e].x, kv.x, a);
                    a = fmaf(qgr[e].y, kv.y, a);
                    a = fmaf(qgr[e].z, kv.z, a);
                    a = fmaf(qgr[e].w, kv.w, a);
                }
                s[jj] = a;
            }
            float cmax = s[0];
            #pragma unroll
            for (int jj = 1; jj < 8; jj++) cmax = fmaxf(cmax, s[jj]);
            float mnew = fmaxf(m, cmax);
            float corr = __expf(m - mnew);
            l *= corr;
            #pragma unroll
            for (int i = 0; i < 16; i++) {
                outr[i].x *= corr; outr[i].y *= corr;
                outr[i].z *= corr; outr[i].w *= corr;
            }
            #pragma unroll
            for (int jj = 0; jj < 8; jj++) {
                float p = __expf(s[jj] - mnew);
                l += p;
                const float* vr = &Vs[(j0 + jj) * 68];
                #pragma unroll
                for (int i = 0; i < 16; i++) {
                    float4 vv = *(const float4*)&vr[i * 4];
                    outr[i].x = fmaf(p, vv.x, outr[i].x);
                    outr[i].y = fmaf(p, vv.y, outr[i].y);
                    outr[i].z = fmaf(p, vv.z, outr[i].z);
                    outr[i].w = fmaf(p, vv.w, outr[i].w);
                }
            }
            m = mnew;
        }
    }

    const float inv = 1.0f / l;
    #pragma unroll
    for (int i = 0; i < 16; i++) {
        float4 o = make_float4(outr[i].x * inv, outr[i].y * inv,
                               outr[i].z * inv, outr[i].w * inv);
        *(float4*)&out[rowq + i * 4] = o;
    }
}

// ---------------------------------------------------------------------------
extern "C" void kernel_launch(void* const* d_in, const int* in_sizes, int n_in,
                              void* d_out, int out_size)
{
    const float* x  = (const float*)d_in[0];
    const float* Wq = (const float*)d_in[1];
    const float* bq = (const float*)d_in[2];
    const float* Wk = (const float*)d_in[3];
    const float* bk = (const float*)d_in[4];
    const float* Wv = (const float*)d_in[5];
    const float* bv = (const float*)d_in[6];
    const float* Wg = (const float*)d_in[7];
    const float* bg = (const float*)d_in[8];
    float* out = (float*)d_out;

    dim3 g1(TOK / 64, EMB / 64, 3);
    qkv_kernel<<<g1, 256>>>(x, Wq, bq, Wk, bk, Wv, bv);

    const int smem2 = (64 * XS + 64 * QSD + 4096 + 2 * BK * WS) * (int)sizeof(float);
    cudaFuncSetAttribute(qg_kernel, cudaFuncAttributeMaxDynamicSharedMemorySize, smem2);
    dim3 g2(TOK / TB, HEADS);
    qg_kernel<<<g2, 256, smem2>>>(x, Wg, bg);

    dim3 g3(SEQ / 128, BATCH * HEADS);
    attn_kernel<<<g3, 128>>>(out);
}

// round 4
// speedup vs baseline: 2.8326x; 2.8326x over previous
#include <cuda_runtime.h>
#include <cuda_bf16.h>
#include <math.h>

#define BATCH 4
#define SEQ   1024
#define EMB   512
#define HEADS 8
#define HD    64
#define TOK   (BATCH*SEQ)     // 4096
#define WGN   32768

// Scratch (device globals; no allocations allowed)
__device__ float g_Q [TOK*EMB];
__device__ float g_K [TOK*EMB];
__device__ float g_V [TOK*EMB];
__device__ float g_QG[TOK*EMB];
__device__ __align__(16) __nv_bfloat16 g_x_hi [TOK*EMB];
__device__ __align__(16) __nv_bfloat16 g_x_lo [TOK*EMB];
__device__ __align__(16) __nv_bfloat16 g_Wg_hi[EMB*WGN];
__device__ __align__(16) __nv_bfloat16 g_Wg_lo[EMB*WGN];

__device__ __forceinline__ unsigned sptr(const void* p) {
    return (unsigned)__cvta_generic_to_shared(p);
}

#define CP16(dst, src) \
    asm volatile("cp.async.cg.shared.global [%0], [%1], 16;\n" :: "r"(dst), "l"(src))

#define LDSM4(R, addr) \
    asm volatile("ldmatrix.sync.aligned.m8n8.x4.shared.b16 {%0,%1,%2,%3}, [%4];\n" \
        : "=r"((R)[0]), "=r"((R)[1]), "=r"((R)[2]), "=r"((R)[3]) : "r"(addr))

#define LDSM4T(R, addr) \
    asm volatile("ldmatrix.sync.aligned.m8n8.x4.trans.shared.b16 {%0,%1,%2,%3}, [%4];\n" \
        : "=r"((R)[0]), "=r"((R)[1]), "=r"((R)[2]), "=r"((R)[3]) : "r"(addr))

#define MMA16816(C, A, b0, b1) \
    asm volatile("mma.sync.aligned.m16n8k16.row.col.f32.bf16.bf16.f32 " \
        "{%0,%1,%2,%3}, {%4,%5,%6,%7}, {%8,%9}, {%0,%1,%2,%3};\n" \
        : "+f"((C)[0]), "+f"((C)[1]), "+f"((C)[2]), "+f"((C)[3]) \
        : "r"((A)[0]), "r"((A)[1]), "r"((A)[2]), "r"((A)[3]), "r"(b0), "r"(b1))

// ---------------------------------------------------------------------------
// Split fp32 -> bf16 hi + bf16 lo (hi+lo ~= fp32 to ~2^-17 relative)
// ---------------------------------------------------------------------------
__global__ void split_kernel(const float* __restrict__ src,
                             __nv_bfloat16* __restrict__ hi,
                             __nv_bfloat16* __restrict__ lo, int n4)
{
    int i = blockIdx.x * blockDim.x + threadIdx.x;
    if (i >= n4) return;
    float4 v = ((const float4*)src)[i];
    float vv[4] = {v.x, v.y, v.z, v.w};
    __nv_bfloat16 h4[4], l4[4];
    #pragma unroll
    for (int j = 0; j < 4; j++) {
        __nv_bfloat16 hh = __float2bfloat16(vv[j]);
        h4[j] = hh;
        l4[j] = __float2bfloat16(vv[j] - __bfloat162float(hh));
    }
    *(uint2*)(hi + 4 * (size_t)i) = *(uint2*)h4;
    *(uint2*)(lo + 4 * (size_t)i) = *(uint2*)l4;
}

// ---------------------------------------------------------------------------
// Kernel 1: QKV projections (unchanged, ~190us)
// ---------------------------------------------------------------------------
__global__ __launch_bounds__(256) void qkv_kernel(
    const float* __restrict__ x,
    const float* __restrict__ Wq, const float* __restrict__ bq,
    const float* __restrict__ Wk, const float* __restrict__ bk,
    const float* __restrict__ Wv, const float* __restrict__ bv)
{
    const int which = blockIdx.z;
    const float* Wm = (which == 0) ? Wq : (which == 1) ? Wk : Wv;
    const float* bm = (which == 0) ? bq : (which == 1) ? bk : bv;
    float* outp     = (which == 0) ? g_Q : (which == 1) ? g_K : g_V;

    __shared__ float As[64 * 20];
    __shared__ float Bs[16 * 68];

    const int tid = threadIdx.x;
    const int tx  = tid & 15;
    const int ty  = tid >> 4;
    const int m0  = blockIdx.x * 64;
    const int n0  = blockIdx.y * 64;

    float acc[4][4] = {};

    for (int k0 = 0; k0 < EMB; k0 += 16) {
        __syncthreads();
        {
            int t  = tid >> 2;
            int c4 = (tid & 3) << 2;
            float4 v = *(const float4*)&x[(size_t)(m0 + t) * EMB + k0 + c4];
            *(float4*)&As[t * 20 + c4] = v;
            int r  = tid >> 4;
            int cc = (tid & 15) << 2;
            float4 w = *(const float4*)&Wm[(size_t)(k0 + r) * EMB + n0 + cc];
            *(float4*)&Bs[r * 68 + cc] = w;
        }
        __syncthreads();
        #pragma unroll
        for (int kk = 0; kk < 16; kk++) {
            float4 w = *(const float4*)&Bs[kk * 68 + tx * 4];
            #pragma unroll
            for (int i = 0; i < 4; i++) {
                float a = As[(ty * 4 + i) * 20 + kk];
                acc[i][0] = fmaf(a, w.x, acc[i][0]);
                acc[i][1] = fmaf(a, w.y, acc[i][1]);
                acc[i][2] = fmaf(a, w.z, acc[i][2]);
                acc[i][3] = fmaf(a, w.w, acc[i][3]);
            }
        }
    }

    const float4 bb = *(const float4*)&bm[n0 + tx * 4];
    #pragma unroll
    for (int i = 0; i < 4; i++) {
        float4 o = make_float4(acc[i][0] + bb.x, acc[i][1] + bb.y,
                               acc[i][2] + bb.z, acc[i][3] + bb.w);
        *(float4*)&outp[(size_t)(m0 + ty * 4 + i) * EMB + n0 + tx * 4] = o;
    }
}

// ---------------------------------------------------------------------------
// Kernel 2 (dominant): tensor-core fused  g = gelu(x@Wg+bg),
// qg[t,h,e] = sum_d q[t,h,d]*g[t,h,d,e].
// bf16 hi/lo split (3 MMAs) for ~fp32 accuracy. CTA = 128 tokens x 1 head.
// 32 N-passes of 128 cols (2 d-values); K=512 via double-buffered cp.async.
// ---------------------------------------------------------------------------
// SMEM layout (bytes):
//   As: [2 buf][2 hi/lo][128 x 40] bf16  = 40960
//   Bs: [2 buf][2 hi/lo][ 32 x136] bf16  = 34816
//   Qs: [128 x 65] f32                   = 33280
//   qg0,qg1: [128 x 66] f32 each         = 67584
#define QG_SMEM (40960 + 34816 + 33280 + 67584)

__global__ __launch_bounds__(256, 1) void qg_mma_kernel(const float* __restrict__ bg)
{
    extern __shared__ char smraw[];
    __nv_bfloat16* As = (__nv_bfloat16*)smraw;          // idx: bsel*10240 + hilo*5120
    __nv_bfloat16* Bs = As + 4 * 128 * 40;              // idx: bsel*8704  + hilo*4352
    float* Qs  = (float*)(Bs + 4 * 32 * 136);
    float* qg0 = Qs + 128 * 65;
    float* qg1 = qg0 + 128 * 66;

    const int tid  = threadIdx.x;
    const int lane = tid & 31;
    const int w    = tid >> 5;
    const int wm   = w & 3;        // M warp (32 rows)
    const int wn   = w >> 2;       // N warp (64 cols = one d)
    const int h    = blockIdx.y;
    const int tok0 = blockIdx.x * 128;

    // Load Q tile [128 tokens x 64 d], pad 65
    #pragma unroll
    for (int it = 0; it < 8; it++) {
        int idx = tid + it * 256;           // float4 id, 0..2047
        int r = idx >> 4, c4 = (idx & 15) << 2;
        float4 v = *(const float4*)&g_Q[(size_t)(tok0 + r) * EMB + h * 64 + c4];
        Qs[r * 65 + c4 + 0] = v.x; Qs[r * 65 + c4 + 1] = v.y;
        Qs[r * 65 + c4 + 2] = v.z; Qs[r * 65 + c4 + 3] = v.w;
    }
    for (int it = tid; it < 128 * 66; it += 256) { qg0[it] = 0.f; qg1[it] = 0.f; }
    __syncthreads();

    const size_t colbase0 = (size_t)h * 4096;

    for (int pass = 0; pass < 32; pass++) {
        float acc[2][8][4];
        #pragma unroll
        for (int a = 0; a < 2; a++)
            #pragma unroll
            for (int b = 0; b < 8; b++)
                #pragma unroll
                for (int cje = 0; cje < 4; cje++) acc[a][b][cje] = 0.f;

        const size_t colbase = colbase0 + (size_t)pass * 128;

        // chunk loader (c = k-chunk index, bsel = target buffer)
        auto issue_chunk = [&](int c, int bsel) {
            const int k0 = c * 32;
            #pragma unroll
            for (int it = 0; it < 2; it++) {
                int idx = tid + it * 256;          // 0..511
                // A: 128 rows x 32 cols (64B data per row)
                int ar = idx >> 2, aseg = (idx & 3) << 3;
                const __nv_bfloat16* sah = &g_x_hi[(size_t)(tok0 + ar) * EMB + k0 + aseg];
                const __nv_bfloat16* sal = &g_x_lo[(size_t)(tok0 + ar) * EMB + k0 + aseg];
                CP16(sptr(&As[bsel * 10240 +        ar * 40 + aseg]), sah);
                CP16(sptr(&As[bsel * 10240 + 5120 + ar * 40 + aseg]), sal);
                // B: 32 rows x 128 cols (256B per row)
                int br = idx >> 4, bseg = (idx & 15) << 3;
                const __nv_bfloat16* sbh = &g_Wg_hi[(size_t)(k0 + br) * WGN + colbase + bseg];
                const __nv_bfloat16* sbl = &g_Wg_lo[(size_t)(k0 + br) * WGN + colbase + bseg];
                CP16(sptr(&Bs[bsel * 8704 +        br * 136 + bseg]), sbh);
                CP16(sptr(&Bs[bsel * 8704 + 4352 + br * 136 + bseg]), sbl);
            }
            asm volatile("cp.async.commit_group;\n");
        };

        issue_chunk(0, 0);
        int bsel = 0;
        for (int c = 0; c < 16; c++) {
            asm volatile("cp.async.wait_group 0;\n");
            __syncthreads();
            if (c < 15) issue_chunk(c + 1, bsel ^ 1);

            const __nv_bfloat16* Ab = As + bsel * 10240;
            const __nv_bfloat16* Bb = Bs + bsel * 8704;
            #pragma unroll
            for (int kk = 0; kk < 2; kk++) {
                unsigned Ah[2][4], Al[2][4], Bh[4][4], Bl[4][4];
                #pragma unroll
                for (int tm = 0; tm < 2; tm++) {
                    unsigned a = sptr(&Ab[(wm * 32 + tm * 16 + (lane & 15)) * 40
                                          + kk * 16 + (lane >> 4) * 8]);
                    LDSM4(Ah[tm], a);
                    LDSM4(Al[tm], a + 5120 * 2);
                }
                #pragma unroll
                for (int tn4 = 0; tn4 < 4; tn4++) {
                    unsigned b = sptr(&Bb[(kk * 16 + (lane & 15)) * 136
                                          + wn * 64 + tn4 * 16 + (lane >> 4) * 8]);
                    LDSM4T(Bh[tn4], b);
                    LDSM4T(Bl[tn4], b + 4352 * 2);
                }
                #pragma unroll
                for (int tm = 0; tm < 2; tm++)
                    #pragma unroll
                    for (int tn4 = 0; tn4 < 4; tn4++)
                        #pragma unroll
                        for (int hlf = 0; hlf < 2; hlf++) {
                            const int tn = tn4 * 2 + hlf;
                            MMA16816(acc[tm][tn], Ah[tm], Bh[tn4][hlf*2], Bh[tn4][hlf*2+1]);
                            MMA16816(acc[tm][tn], Ah[tm], Bl[tn4][hlf*2], Bl[tn4][hlf*2+1]);
                            MMA16816(acc[tm][tn], Al[tm], Bh[tn4][hlf*2], Bh[tn4][hlf*2+1]);
                        }
            }
            bsel ^= 1;
        }

        // Epilogue: bias + exact GELU + q-weighted accumulate over d.
        // Warp's N-half selects d = pass*2 + wn; its own qg buffer -> no races.
        float* qgb = wn ? qg1 : qg0;
        const int dg = pass * 2 + wn;
        const float* bgp = &bg[colbase0 * 8 / 8];  // = bg + h*4096 (kept simple below)
        #pragma unroll
        for (int tm = 0; tm < 2; tm++) {
            const int r0 = wm * 32 + tm * 16 + (lane >> 2);
            const float q0 = Qs[r0 * 65 + dg];
            const float q1 = Qs[(r0 + 8) * 65 + dg];
            #pragma unroll
            for (int tn = 0; tn < 8; tn++) {
                const int e = tn * 8 + (lane & 3) * 2;
                const float b0 = __ldg(&bg[(size_t)h * 4096 + dg * 64 + e]);
                const float b1 = __ldg(&bg[(size_t)h * 4096 + dg * 64 + e + 1]);
                float s0 = acc[tm][tn][0] + b0;
                float s1 = acc[tm][tn][1] + b1;
                float s2 = acc[tm][tn][2] + b0;
                float s3 = acc[tm][tn][3] + b1;
                const float k = 0.70710678118654752f;
                float g0 = 0.5f * s0 * (1.0f + erff(s0 * k));
                float g1 = 0.5f * s1 * (1.0f + erff(s1 * k));
                float g2 = 0.5f * s2 * (1.0f + erff(s2 * k));
                float g3 = 0.5f * s3 * (1.0f + erff(s3 * k));
                qgb[r0 * 66 + e]           += q0 * g0;
                qgb[r0 * 66 + e + 1]       += q0 * g1;
                qgb[(r0 + 8) * 66 + e]     += q1 * g2;
                qgb[(r0 + 8) * 66 + e + 1] += q1 * g3;
            }
        }
        (void)bgp;
    }

    __syncthreads();
    for (int it = tid; it < 128 * 64; it += 256) {
        int r = it >> 6, e = it & 63;
        g_QG[(size_t)(tok0 + r) * EMB + h * 64 + e] = qg0[r * 66 + e] + qg1[r * 66 + e];
    }
}

// ---------------------------------------------------------------------------
// Kernel 3: flash-style attention (unchanged)
// ---------------------------------------------------------------------------
__global__ __launch_bounds__(128) void attn_kernel(float* __restrict__ out)
{
    __shared__ float Ks[64 * 68];
    __shared__ float Vs[64 * 68];

    const int bh  = blockIdx.y;
    const int b   = bh >> 3;
    const int h   = bh & 7;
    const int tid = threadIdx.x;
    const int n   = blockIdx.x * 128 + tid;
    const size_t rowq = (size_t)(b * SEQ + n) * EMB + h * 64;

    float4 qgr[16], outr[16];
    #pragma unroll
    for (int i = 0; i < 16; i++) {
        qgr[i]  = *(const float4*)&g_QG[rowq + i * 4];
        outr[i] = make_float4(0.f, 0.f, 0.f, 0.f);
    }
    float m = -INFINITY, l = 0.f;

    for (int kb = 0; kb < 16; kb++) {
        __syncthreads();
        #pragma unroll
        for (int it = 0; it < 8; it++) {
            int idx = tid + it * 128;
            int r   = idx >> 4;
            int c4  = (idx & 15) << 2;
            size_t g = (size_t)(b * SEQ + kb * 64 + r) * EMB + h * 64 + c4;
            *(float4*)&Ks[r * 68 + c4] = *(const float4*)&g_K[g];
            *(float4*)&Vs[r * 68 + c4] = *(const float4*)&g_V[g];
        }
        __syncthreads();

        #pragma unroll 1
        for (int j0 = 0; j0 < 64; j0 += 8) {
            float s[8];
            #pragma unroll
            for (int jj = 0; jj < 8; jj++) {
                const float* kr = &Ks[(j0 + jj) * 68];
                float a = 0.f;
                #pragma unroll
                for (int e = 0; e < 16; e++) {
                    float4 kv = *(const float4*)&kr[e * 4];
                    a = fmaf(qgr[e].x, kv.x, a);
                    a = fmaf(qgr[e].y, kv.y, a);
                    a = fmaf(qgr[e].z, kv.z, a);
                    a = fmaf(qgr[e].w, kv.w, a);
                }
                s[jj] = a;
            }
            float cmax = s[0];
            #pragma unroll
            for (int jj = 1; jj < 8; jj++) cmax = fmaxf(cmax, s[jj]);
            float mnew = fmaxf(m, cmax);
            float corr = __expf(m - mnew);
            l *= corr;
            #pragma unroll
            for (int i = 0; i < 16; i++) {
                outr[i].x *= corr; outr[i].y *= corr;
                outr[i].z *= corr; outr[i].w *= corr;
            }
            #pragma unroll
            for (int jj = 0; jj < 8; jj++) {
                float p = __expf(s[jj] - mnew);
                l += p;
                const float* vr = &Vs[(j0 + jj) * 68];
                #pragma unroll
                for (int i = 0; i < 16; i++) {
                    float4 vv = *(const float4*)&vr[i * 4];
                    outr[i].x = fmaf(p, vv.x, outr[i].x);
                    outr[i].y = fmaf(p, vv.y, outr[i].y);
                    outr[i].z = fmaf(p, vv.z, outr[i].z);
                    outr[i].w = fmaf(p, vv.w, outr[i].w);
                }
            }
            m = mnew;
        }
    }

    const float inv = 1.0f / l;
    #pragma unroll
    for (int i = 0; i < 16; i++) {
        float4 o = make_float4(outr[i].x * inv, outr[i].y * inv,
                               outr[i].z * inv, outr[i].w * inv);
        *(float4*)&out[rowq + i * 4] = o;
    }
}

// ---------------------------------------------------------------------------
extern "C" void kernel_launch(void* const* d_in, const int* in_sizes, int n_in,
                              void* d_out, int out_size)
{
    const float* x  = (const float*)d_in[0];
    const float* Wq = (const float*)d_in[1];
    const float* bq = (const float*)d_in[2];
    const float* Wk = (const float*)d_in[3];
    const float* bk = (const float*)d_in[4];
    const float* Wv = (const float*)d_in[5];
    const float* bv = (const float*)d_in[6];
    const float* Wg = (const float*)d_in[7];
    const float* bg = (const float*)d_in[8];
    float* out = (float*)d_out;

    // Resolve device-global scratch addresses for the split kernels
    __nv_bfloat16 *xhi, *xlo, *whi, *wlo;
    cudaGetSymbolAddress((void**)&xhi, g_x_hi);
    cudaGetSymbolAddress((void**)&xlo, g_x_lo);
    cudaGetSymbolAddress((void**)&whi, g_Wg_hi);
    cudaGetSymbolAddress((void**)&wlo, g_Wg_lo);

    {   // split x: 4096*512/4 = 524288 float4s
        int n4 = TOK * EMB / 4;
        split_kernel<<<(n4 + 255) / 256, 256>>>(x, xhi, xlo, n4);
    }
    {   // split Wg: 512*32768/4 = 4194304 float4s
        int n4 = EMB * WGN / 4;
        split_kernel<<<(n4 + 255) / 256, 256>>>(Wg, whi, wlo, n4);
    }

    dim3 g1(TOK / 64, EMB / 64, 3);
    qkv_kernel<<<g1, 256>>>(x, Wq, bq, Wk, bk, Wv, bv);

    cudaFuncSetAttribute(qg_mma_kernel, cudaFuncAttributeMaxDynamicSharedMemorySize, QG_SMEM);
    dim3 g2(TOK / 128, HEADS);
    qg_mma_kernel<<<g2, 256, QG_SMEM>>>(bg);

    dim3 g3(SEQ / 128, BATCH * HEADS);
    attn_kernel<<<g3, 128>>>(out);
}

// round 7
// speedup vs baseline: 2.8856x; 1.0187x over previous
#include <cuda_runtime.h>
#include <cuda_bf16.h>
#include <math.h>

#define BATCH 4
#define SEQ   1024
#define EMB   512
#define HEADS 8
#define HD    64
#define TOK   (BATCH*SEQ)     // 4096
#define WGN   32768

// Scratch (device globals; no allocations allowed)
__device__ float g_Q [TOK*EMB];
__device__ float g_K [TOK*EMB];
__device__ float g_V [TOK*EMB];
__device__ float g_QG[TOK*EMB];
__device__ __align__(16) __nv_bfloat16 g_x_hi [TOK*EMB];
__device__ __align__(16) __nv_bfloat16 g_x_lo [TOK*EMB];
__device__ __align__(16) __nv_bfloat16 g_Wg_hi[(size_t)EMB*WGN];
__device__ __align__(16) __nv_bfloat16 g_Wg_lo[(size_t)EMB*WGN];

__device__ __forceinline__ unsigned sptr(const void* p) {
    return (unsigned)__cvta_generic_to_shared(p);
}

#define CP16(dst, src) \
    asm volatile("cp.async.cg.shared.global [%0], [%1], 16;\n" :: "r"(dst), "l"(src))

#define LDSM4(R, addr) \
    asm volatile("ldmatrix.sync.aligned.m8n8.x4.shared.b16 {%0,%1,%2,%3}, [%4];\n" \
        : "=r"((R)[0]), "=r"((R)[1]), "=r"((R)[2]), "=r"((R)[3]) : "r"(addr))

#define LDSM4T(R, addr) \
    asm volatile("ldmatrix.sync.aligned.m8n8.x4.trans.shared.b16 {%0,%1,%2,%3}, [%4];\n" \
        : "=r"((R)[0]), "=r"((R)[1]), "=r"((R)[2]), "=r"((R)[3]) : "r"(addr))

#define MMA16816(C, A, b0, b1) \
    asm volatile("mma.sync.aligned.m16n8k16.row.col.f32.bf16.bf16.f32 " \
        "{%0,%1,%2,%3}, {%4,%5,%6,%7}, {%8,%9}, {%0,%1,%2,%3};\n" \
        : "+f"((C)[0]), "+f"((C)[1]), "+f"((C)[2]), "+f"((C)[3]) \
        : "r"((A)[0]), "r"((A)[1]), "r"((A)[2]), "r"((A)[3]), "r"(b0), "r"(b1))

// ---------------------------------------------------------------------------
// Split fp32 -> bf16 hi + bf16 lo
// ---------------------------------------------------------------------------
__global__ void split_kernel(const float* __restrict__ src,
                             __nv_bfloat16* __restrict__ hi,
                             __nv_bfloat16* __restrict__ lo, int n4)
{
    int i = blockIdx.x * blockDim.x + threadIdx.x;
    if (i >= n4) return;
    float4 v = ((const float4*)src)[i];
    float vv[4] = {v.x, v.y, v.z, v.w};
    __nv_bfloat16 h4[4], l4[4];
    #pragma unroll
    for (int j = 0; j < 4; j++) {
        __nv_bfloat16 hh = __float2bfloat16(vv[j]);
        h4[j] = hh;
        l4[j] = __float2bfloat16(vv[j] - __bfloat162float(hh));
    }
    *(uint2*)(hi + 4 * (size_t)i) = *(uint2*)h4;
    *(uint2*)(lo + 4 * (size_t)i) = *(uint2*)l4;
}

// ---------------------------------------------------------------------------
// Kernel 1: QKV projections (unchanged)
// ---------------------------------------------------------------------------
__global__ __launch_bounds__(256) void qkv_kernel(
    const float* __restrict__ x,
    const float* __restrict__ Wq, const float* __restrict__ bq,
    const float* __restrict__ Wk, const float* __restrict__ bk,
    const float* __restrict__ Wv, const float* __restrict__ bv)
{
    const int which = blockIdx.z;
    const float* Wm = (which == 0) ? Wq : (which == 1) ? Wk : Wv;
    const float* bm = (which == 0) ? bq : (which == 1) ? bk : bv;
    float* outp     = (which == 0) ? g_Q : (which == 1) ? g_K : g_V;

    __shared__ float As[64 * 20];
    __shared__ float Bs[16 * 68];

    const int tid = threadIdx.x;
    const int tx  = tid & 15;
    const int ty  = tid >> 4;
    const int m0  = blockIdx.x * 64;
    const int n0  = blockIdx.y * 64;

    float acc[4][4] = {};

    for (int k0 = 0; k0 < EMB; k0 += 16) {
        __syncthreads();
        {
            int t  = tid >> 2;
            int c4 = (tid & 3) << 2;
            float4 v = *(const float4*)&x[(size_t)(m0 + t) * EMB + k0 + c4];
            *(float4*)&As[t * 20 + c4] = v;
            int r  = tid >> 4;
            int cc = (tid & 15) << 2;
            float4 w = *(const float4*)&Wm[(size_t)(k0 + r) * EMB + n0 + cc];
            *(float4*)&Bs[r * 68 + cc] = w;
        }
        __syncthreads();
        #pragma unroll
        for (int kk = 0; kk < 16; kk++) {
            float4 w = *(const float4*)&Bs[kk * 68 + tx * 4];
            #pragma unroll
            for (int i = 0; i < 4; i++) {
                float a = As[(ty * 4 + i) * 20 + kk];
                acc[i][0] = fmaf(a, w.x, acc[i][0]);
                acc[i][1] = fmaf(a, w.y, acc[i][1]);
                acc[i][2] = fmaf(a, w.z, acc[i][2]);
                acc[i][3] = fmaf(a, w.w, acc[i][3]);
            }
        }
    }

    const float4 bb = *(const float4*)&bm[n0 + tx * 4];
    #pragma unroll
    for (int i = 0; i < 4; i++) {
        float4 o = make_float4(acc[i][0] + bb.x, acc[i][1] + bb.y,
                               acc[i][2] + bb.z, acc[i][3] + bb.w);
        *(float4*)&outp[(size_t)(m0 + ty * 4 + i) * EMB + n0 + tx * 4] = o;
    }
}

// ---------------------------------------------------------------------------
// Kernel 2 (dominant): HMMA fused  g = gelu(x@Wg+bg), qg = sum_d q_d * g_d
// CTA = 128 tokens x 1 head, 256 threads (8 warps: wm=w&3 M-rows, wn=w>>2 the
// d within the pass). 32 passes x N=128 (2 d's); K=512 in double-buffered
// 32-wide cp.async chunks. bf16 hi/lo 3-product split, fp32 accumulate.
// qg accumulator lives in REGISTERS (pass-invariant fragment positions);
// one cross-parity SMEM reduction at the end.
// SMEM: As 40960 | Bs 34816 | Qs 33280  = 109056 bytes
// ---------------------------------------------------------------------------
#define QG_SMEM 109056

__global__ __launch_bounds__(256, 1) void qg_mma_kernel(const float* __restrict__ bg)
{
    extern __shared__ char smraw[];
    __nv_bfloat16* As = (__nv_bfloat16*)smraw;          // idx: bsel*10240 + hilo*5120
    __nv_bfloat16* Bs = As + 4 * 128 * 40;              // idx: bsel*8704  + hilo*4352
    float* Qs  = (float*)(Bs + 4 * 32 * 136);           // [128 x 65]

    const int tid  = threadIdx.x;
    const int lane = tid & 31;
    const int w    = tid >> 5;
    const int wm   = w & 3;        // M warp (32 rows)
    const int wn   = w >> 2;       // d parity within pass
    const int h    = blockIdx.y;
    const int tok0 = blockIdx.x * 128;

    // Load Q tile [128 tokens x 64 d], pad 65
    #pragma unroll
    for (int it = 0; it < 8; it++) {
        int idx = tid + it * 256;           // float4 id, 0..2047
        int r = idx >> 4, c4 = (idx & 15) << 2;
        float4 v = *(const float4*)&g_Q[(size_t)(tok0 + r) * EMB + h * 64 + c4];
        Qs[r * 65 + c4 + 0] = v.x; Qs[r * 65 + c4 + 1] = v.y;
        Qs[r * 65 + c4 + 2] = v.z; Qs[r * 65 + c4 + 3] = v.w;
    }
    __syncthreads();

    // Register-resident qg accumulator: [tm][rowhalf][tn][j]
    float qg[2][2][8][2];
    #pragma unroll
    for (int a = 0; a < 2; a++)
        #pragma unroll
        for (int b = 0; b < 2; b++)
            #pragma unroll
            for (int c = 0; c < 8; c++) { qg[a][b][c][0] = 0.f; qg[a][b][c][1] = 0.f; }

    const size_t colbase0 = (size_t)h * 4096;
    const float kgelu = 0.70710678118654752f;

    for (int pass = 0; pass < 32; pass++) {
        float acc[2][8][4];
        #pragma unroll
        for (int a = 0; a < 2; a++)
            #pragma unroll
            for (int b = 0; b < 8; b++)
                #pragma unroll
                for (int cje = 0; cje < 4; cje++) acc[a][b][cje] = 0.f;

        const size_t colbase = colbase0 + (size_t)pass * 128;

        auto issue_chunk = [&](int c, int bsel) {
            const int k0 = c * 32;
            #pragma unroll
            for (int it = 0; it < 2; it++) {
                int idx = tid + it * 256;          // 0..511
                // A: 128 rows x 32 cols
                int ar = idx >> 2, aseg = (idx & 3) << 3;
                const __nv_bfloat16* sah = &g_x_hi[(size_t)(tok0 + ar) * EMB + k0 + aseg];
                const __nv_bfloat16* sal = &g_x_lo[(size_t)(tok0 + ar) * EMB + k0 + aseg];
                CP16(sptr(&As[bsel * 10240 +        ar * 40 + aseg]), sah);
                CP16(sptr(&As[bsel * 10240 + 5120 + ar * 40 + aseg]), sal);
                // B: 32 rows x 128 cols
                int br = idx >> 4, bseg = (idx & 15) << 3;
                const __nv_bfloat16* sbh = &g_Wg_hi[(size_t)(k0 + br) * WGN + colbase + bseg];
                const __nv_bfloat16* sbl = &g_Wg_lo[(size_t)(k0 + br) * WGN + colbase + bseg];
                CP16(sptr(&Bs[bsel * 8704 +        br * 136 + bseg]), sbh);
                CP16(sptr(&Bs[bsel * 8704 + 4352 + br * 136 + bseg]), sbl);
            }
            asm volatile("cp.async.commit_group;\n");
        };

        issue_chunk(0, 0);
        int bsel = 0;
        for (int c = 0; c < 16; c++) {
            asm volatile("cp.async.wait_group 0;\n");
            __syncthreads();
            if (c < 15) issue_chunk(c + 1, bsel ^ 1);

            const __nv_bfloat16* Ab = As + bsel * 10240;
            const __nv_bfloat16* Bb = Bs + bsel * 8704;
            #pragma unroll
            for (int kk = 0; kk < 2; kk++) {
                unsigned Ah[2][4], Al[2][4], Bh[4][4], Bl[4][4];
                #pragma unroll
                for (int tm = 0; tm < 2; tm++) {
                    unsigned a = sptr(&Ab[(wm * 32 + tm * 16 + (lane & 15)) * 40
                                          + kk * 16 + (lane >> 4) * 8]);
                    LDSM4(Ah[tm], a);
                    LDSM4(Al[tm], a + 5120 * 2);
                }
                #pragma unroll
                for (int tn4 = 0; tn4 < 4; tn4++) {
                    unsigned b = sptr(&Bb[(kk * 16 + (lane & 15)) * 136
                                          + wn * 64 + tn4 * 16 + (lane >> 4) * 8]);
                    LDSM4T(Bh[tn4], b);
                    LDSM4T(Bl[tn4], b + 4352 * 2);
                }
                #pragma unroll
                for (int tm = 0; tm < 2; tm++)
                    #pragma unroll
                    for (int tn4 = 0; tn4 < 4; tn4++)
                        #pragma unroll
                        for (int hlf = 0; hlf < 2; hlf++) {
                            const int tn = tn4 * 2 + hlf;
                            MMA16816(acc[tm][tn], Ah[tm], Bh[tn4][hlf*2], Bh[tn4][hlf*2+1]);
                            MMA16816(acc[tm][tn], Ah[tm], Bl[tn4][hlf*2], Bl[tn4][hlf*2+1]);
                            MMA16816(acc[tm][tn], Al[tm], Bh[tn4][hlf*2], Bh[tn4][hlf*2+1]);
                        }
            }
            bsel ^= 1;
        }

        // Epilogue: bias + exact GELU + q-weighted accumulate into REGISTERS.
        const int dg = pass * 2 + wn;
        #pragma unroll
        for (int tm = 0; tm < 2; tm++) {
            const int r0 = wm * 32 + tm * 16 + (lane >> 2);
            const float q0 = Qs[r0 * 65 + dg];
            const float q1 = Qs[(r0 + 8) * 65 + dg];
            #pragma unroll
            for (int tn = 0; tn < 8; tn++) {
                const int e = tn * 8 + (lane & 3) * 2;
                const float b0 = __ldg(&bg[(size_t)h * 4096 + dg * 64 + e]);
                const float b1 = __ldg(&bg[(size_t)h * 4096 + dg * 64 + e + 1]);
                float s0 = acc[tm][tn][0] + b0;
                float s1 = acc[tm][tn][1] + b1;
                float s2 = acc[tm][tn][2] + b0;
                float s3 = acc[tm][tn][3] + b1;
                float g0 = 0.5f * s0 * (1.0f + erff(s0 * kgelu));
                float g1 = 0.5f * s1 * (1.0f + erff(s1 * kgelu));
                float g2 = 0.5f * s2 * (1.0f + erff(s2 * kgelu));
                float g3 = 0.5f * s3 * (1.0f + erff(s3 * kgelu));
                qg[tm][0][tn][0] = fmaf(q0, g0, qg[tm][0][tn][0]);
                qg[tm][0][tn][1] = fmaf(q0, g1, qg[tm][0][tn][1]);
                qg[tm][1][tn][0] = fmaf(q1, g2, qg[tm][1][tn][0]);
                qg[tm][1][tn][1] = fmaf(q1, g3, qg[tm][1][tn][1]);
            }
        }
    }

    // Cross-parity reduction: wn=1 warps stage to SMEM (reuse As region),
    // wn=0 warps add and write to gmem.
    __syncthreads();                       // all MMA reads of As done
    float* red = (float*)smraw;            // [128 rows][64 e] = 32KB
    if (wn == 1) {
        #pragma unroll
        for (int tm = 0; tm < 2; tm++)
            #pragma unroll
            for (int rh = 0; rh < 2; rh++) {
                const int row = wm * 32 + tm * 16 + rh * 8 + (lane >> 2);
                #pragma unroll
                for (int tn = 0; tn < 8; tn++) {
                    const int e = tn * 8 + (lane & 3) * 2;
                    red[row * 64 + e]     = qg[tm][rh][tn][0];
                    red[row * 64 + e + 1] = qg[tm][rh][tn][1];
                }
            }
    }
    __syncthreads();
    if (wn == 0) {
        #pragma unroll
        for (int tm = 0; tm < 2; tm++)
            #pragma unroll
            for (int rh = 0; rh < 2; rh++) {
                const int row = wm * 32 + tm * 16 + rh * 8 + (lane >> 2);
                #pragma unroll
                for (int tn = 0; tn < 8; tn++) {
                    const int e = tn * 8 + (lane & 3) * 2;
                    float2 o;
                    o.x = qg[tm][rh][tn][0] + red[row * 64 + e];
                    o.y = qg[tm][rh][tn][1] + red[row * 64 + e + 1];
                    *(float2*)&g_QG[(size_t)(tok0 + row) * EMB + h * 64 + e] = o;
                }
            }
    }
}

// ---------------------------------------------------------------------------
// Kernel 3: flash-style attention (unchanged)
// ---------------------------------------------------------------------------
__global__ __launch_bounds__(128) void attn_kernel(float* __restrict__ out)
{
    __shared__ float Ks[64 * 68];
    __shared__ float Vs[64 * 68];

    const int bh  = blockIdx.y;
    const int b   = bh >> 3;
    const int h   = bh & 7;
    const int tid = threadIdx.x;
    const int n   = blockIdx.x * 128 + tid;
    const size_t rowq = (size_t)(b * SEQ + n) * EMB + h * 64;

    float4 qgr[16], outr[16];
    #pragma unroll
    for (int i = 0; i < 16; i++) {
        qgr[i]  = *(const float4*)&g_QG[rowq + i * 4];
        outr[i] = make_float4(0.f, 0.f, 0.f, 0.f);
    }
    float m = -INFINITY, l = 0.f;

    for (int kb = 0; kb < 16; kb++) {
        __syncthreads();
        #pragma unroll
        for (int it = 0; it < 8; it++) {
            int idx = tid + it * 128;
            int r   = idx >> 4;
            int c4  = (idx & 15) << 2;
            size_t g = (size_t)(b * SEQ + kb * 64 + r) * EMB + h * 64 + c4;
            *(float4*)&Ks[r * 68 + c4] = *(const float4*)&g_K[g];
            *(float4*)&Vs[r * 68 + c4] = *(const float4*)&g_V[g];
        }
        __syncthreads();

        #pragma unroll 1
        for (int j0 = 0; j0 < 64; j0 += 8) {
            float s[8];
            #pragma unroll
            for (int jj = 0; jj < 8; jj++) {
                const float* kr = &Ks[(j0 + jj) * 68];
                float a = 0.f;
                #pragma unroll
                for (int e = 0; e < 16; e++) {
                    float4 kv = *(const float4*)&kr[e * 4];
                    a = fmaf(qgr[e].x, kv.x, a);
                    a = fmaf(qgr[e].y, kv.y, a);
                    a = fmaf(qgr[e].z, kv.z, a);
                    a = fmaf(qgr[e].w, kv.w, a);
                }
                s[jj] = a;
            }
            float cmax = s[0];
            #pragma unroll
            for (int jj = 1; jj < 8; jj++) cmax = fmaxf(cmax, s[jj]);
            float mnew = fmaxf(m, cmax);
            float corr = __expf(m - mnew);
            l *= corr;
            #pragma unroll
            for (int i = 0; i < 16; i++) {
                outr[i].x *= corr; outr[i].y *= corr;
                outr[i].z *= corr; outr[i].w *= corr;
            }
            #pragma unroll
            for (int jj = 0; jj < 8; jj++) {
                float p = __expf(s[jj] - mnew);
                l += p;
                const float* vr = &Vs[(j0 + jj) * 68];
                #pragma unroll
                for (int i = 0; i < 16; i++) {
                    float4 vv = *(const float4*)&vr[i * 4];
                    outr[i].x = fmaf(p, vv.x, outr[i].x);
                    outr[i].y = fmaf(p, vv.y, outr[i].y);
                    outr[i].z = fmaf(p, vv.z, outr[i].z);
                    outr[i].w = fmaf(p, vv.w, outr[i].w);
                }
            }
            m = mnew;
        }
    }

    const float inv = 1.0f / l;
    #pragma unroll
    for (int i = 0; i < 16; i++) {
        float4 o = make_float4(outr[i].x * inv, outr[i].y * inv,
                               outr[i].z * inv, outr[i].w * inv);
        *(float4*)&out[rowq + i * 4] = o;
    }
}

// ---------------------------------------------------------------------------
extern "C" void kernel_launch(void* const* d_in, const int* in_sizes, int n_in,
                              void* d_out, int out_size)
{
    const float* x  = (const float*)d_in[0];
    const float* Wq = (const float*)d_in[1];
    const float* bq = (const float*)d_in[2];
    const float* Wk = (const float*)d_in[3];
    const float* bk = (const float*)d_in[4];
    const float* Wv = (const float*)d_in[5];
    const float* bv = (const float*)d_in[6];
    const float* Wg = (const float*)d_in[7];
    const float* bg = (const float*)d_in[8];
    float* out = (float*)d_out;

    __nv_bfloat16 *xhi, *xlo, *whi, *wlo;
    cudaGetSymbolAddress((void**)&xhi, g_x_hi);
    cudaGetSymbolAddress((void**)&xlo, g_x_lo);
    cudaGetSymbolAddress((void**)&whi, g_Wg_hi);
    cudaGetSymbolAddress((void**)&wlo, g_Wg_lo);

    {   // split x
        int n4 = TOK * EMB / 4;
        split_kernel<<<(n4 + 255) / 256, 256>>>(x, xhi, xlo, n4);
    }
    {   // split Wg (kept K-major [K, N])
        int n4 = EMB * WGN / 4;
        split_kernel<<<(n4 + 255) / 256, 256>>>(Wg, whi, wlo, n4);
    }

    dim3 g1(TOK / 64, EMB / 64, 3);
    qkv_kernel<<<g1, 256>>>(x, Wq, bq, Wk, bk, Wv, bv);

    cudaFuncSetAttribute(qg_mma_kernel, cudaFuncAttributeMaxDynamicSharedMemorySize, QG_SMEM);
    dim3 g2(TOK / 128, HEADS);
    qg_mma_kernel<<<g2, 256, QG_SMEM>>>(bg);

    dim3 g3(SEQ / 128, BATCH * HEADS);
    attn_kernel<<<g3, 128>>>(out);
}

// round 10
// speedup vs baseline: 3.0586x; 1.0600x over previous
#include <cuda_runtime.h>
#include <cuda_bf16.h>
#include <math.h>

#define BATCH 4
#define SEQ   1024
#define EMB   512
#define HEADS 8
#define HD    64
#define TOK   (BATCH*SEQ)     // 4096
#define WGN   32768

// Scratch (device globals; no allocations allowed)
__device__ float g_Q [TOK*EMB];
__device__ float g_K [TOK*EMB];
__device__ float g_V [TOK*EMB];
__device__ float g_QG[TOK*EMB];
__device__ __align__(16) __nv_bfloat16 g_x_hi [TOK*EMB];
__device__ __align__(16) __nv_bfloat16 g_x_lo [TOK*EMB];
__device__ __align__(16) __nv_bfloat16 g_Wg_hi[(size_t)EMB*WGN];
__device__ __align__(16) __nv_bfloat16 g_Wg_lo[(size_t)EMB*WGN];

__device__ __forceinline__ unsigned sptr(const void* p) {
    return (unsigned)__cvta_generic_to_shared(p);
}

#define CP16CG(dst, src) \
    asm volatile("cp.async.cg.shared.global [%0], [%1], 16;\n" :: "r"(dst), "l"(src))
#define CP16CA(dst, src) \
    asm volatile("cp.async.ca.shared.global [%0], [%1], 16;\n" :: "r"(dst), "l"(src))

#define LDSM4(R, addr) \
    asm volatile("ldmatrix.sync.aligned.m8n8.x4.shared.b16 {%0,%1,%2,%3}, [%4];\n" \
        : "=r"((R)[0]), "=r"((R)[1]), "=r"((R)[2]), "=r"((R)[3]) : "r"(addr))

#define LDSM4T(R, addr) \
    asm volatile("ldmatrix.sync.aligned.m8n8.x4.trans.shared.b16 {%0,%1,%2,%3}, [%4];\n" \
        : "=r"((R)[0]), "=r"((R)[1]), "=r"((R)[2]), "=r"((R)[3]) : "r"(addr))

#define MMA16816(C, A, b0, b1) \
    asm volatile("mma.sync.aligned.m16n8k16.row.col.f32.bf16.bf16.f32 " \
        "{%0,%1,%2,%3}, {%4,%5,%6,%7}, {%8,%9}, {%0,%1,%2,%3};\n" \
        : "+f"((C)[0]), "+f"((C)[1]), "+f"((C)[2]), "+f"((C)[3]) \
        : "r"((A)[0]), "r"((A)[1]), "r"((A)[2]), "r"((A)[3]), "r"(b0), "r"(b1))

// ---------------------------------------------------------------------------
// Split fp32 -> bf16 hi + bf16 lo
// ---------------------------------------------------------------------------
__global__ void split_kernel(const float* __restrict__ src,
                             __nv_bfloat16* __restrict__ hi,
                             __nv_bfloat16* __restrict__ lo, int n4)
{
    int i = blockIdx.x * blockDim.x + threadIdx.x;
    if (i >= n4) return;
    float4 v = ((const float4*)src)[i];
    float vv[4] = {v.x, v.y, v.z, v.w};
    __nv_bfloat16 h4[4], l4[4];
    #pragma unroll
    for (int j = 0; j < 4; j++) {
        __nv_bfloat16 hh = __float2bfloat16(vv[j]);
        h4[j] = hh;
        l4[j] = __float2bfloat16(vv[j] - __bfloat162float(hh));
    }
    *(uint2*)(hi + 4 * (size_t)i) = *(uint2*)h4;
    *(uint2*)(lo + 4 * (size_t)i) = *(uint2*)l4;
}

// ---------------------------------------------------------------------------
// Kernel 1: QKV projections (unchanged)
// ---------------------------------------------------------------------------
__global__ __launch_bounds__(256) void qkv_kernel(
    const float* __restrict__ x,
    const float* __restrict__ Wq, const float* __restrict__ bq,
    const float* __restrict__ Wk, const float* __restrict__ bk,
    const float* __restrict__ Wv, const float* __restrict__ bv)
{
    const int which = blockIdx.z;
    const float* Wm = (which == 0) ? Wq : (which == 1) ? Wk : Wv;
    const float* bm = (which == 0) ? bq : (which == 1) ? bk : bv;
    float* outp     = (which == 0) ? g_Q : (which == 1) ? g_K : g_V;

    __shared__ float As[64 * 20];
    __shared__ float Bs[16 * 68];

    const int tid = threadIdx.x;
    const int tx  = tid & 15;
    const int ty  = tid >> 4;
    const int m0  = blockIdx.x * 64;
    const int n0  = blockIdx.y * 64;

    float acc[4][4] = {};

    for (int k0 = 0; k0 < EMB; k0 += 16) {
        __syncthreads();
        {
            int t  = tid >> 2;
            int c4 = (tid & 3) << 2;
            float4 v = *(const float4*)&x[(size_t)(m0 + t) * EMB + k0 + c4];
            *(float4*)&As[t * 20 + c4] = v;
            int r  = tid >> 4;
            int cc = (tid & 15) << 2;
            float4 w = *(const float4*)&Wm[(size_t)(k0 + r) * EMB + n0 + cc];
            *(float4*)&Bs[r * 68 + cc] = w;
        }
        __syncthreads();
        #pragma unroll
        for (int kk = 0; kk < 16; kk++) {
            float4 w = *(const float4*)&Bs[kk * 68 + tx * 4];
            #pragma unroll
            for (int i = 0; i < 4; i++) {
                float a = As[(ty * 4 + i) * 20 + kk];
                acc[i][0] = fmaf(a, w.x, acc[i][0]);
                acc[i][1] = fmaf(a, w.y, acc[i][1]);
                acc[i][2] = fmaf(a, w.z, acc[i][2]);
                acc[i][3] = fmaf(a, w.w, acc[i][3]);
            }
        }
    }

    const float4 bb = *(const float4*)&bm[n0 + tx * 4];
    #pragma unroll
    for (int i = 0; i < 4; i++) {
        float4 o = make_float4(acc[i][0] + bb.x, acc[i][1] + bb.y,
                               acc[i][2] + bb.z, acc[i][3] + bb.w);
        *(float4*)&outp[(size_t)(m0 + ty * 4 + i) * EMB + n0 + tx * 4] = o;
    }
}

// ---------------------------------------------------------------------------
// Kernel 2 (dominant): HMMA fused  g = gelu(x@Wg+bg), qg = sum_d q_d * g_d
// CTA = 128 tokens x 1 head, 256 threads, __launch_bounds__(256,2): two CTAs
// per SM (grid 256 -> one wave of 296 slots; 4 warps/SMSP).
// 64 passes (one d = 64 N-cols each); K=512 in double-buffered 64-wide
// cp.async chunks (A via .ca to stay L1-resident across passes, B via .cg).
// Warp grid: 4 M-warps (32 rows) x 2 N-warps (32 cols). bf16 hi/lo
// 3-product split, fp32 accumulate. qg fully register-resident; each (row,e)
// owned by exactly one thread -> direct gmem store, no reduction.
// SMEM: A 2stg x 2hilo x 128x72 bf16 (73728B) + B 2x2 x 64x72 (36864B)
// ---------------------------------------------------------------------------
#define APAD 72
#define A_HILO_BYTES 18432            // 128*72*2
#define A_STG_BYTES  36864            // 2 hilo
#define B_HILO_BYTES 9216             // 64*72*2
#define B_STG_BYTES  18432
#define OFF_B        73728            // after A (2 stages)
#define QG_SMEM      110592

__global__ __launch_bounds__(256, 2) void qg_mma_kernel(const float* __restrict__ bg)
{
    extern __shared__ char smraw[];

    const int tid  = threadIdx.x;
    const int lane = tid & 31;
    const int w    = tid >> 5;
    const int wm   = w & 3;        // M warp (32 rows)
    const int wn   = w >> 2;       // N warp (32 cols within the d)
    const int h    = blockIdx.y;
    const int tok0 = blockIdx.x * 128;

    // Register-resident qg accumulator: [tm][rowhalf][tn][j]
    float qg[2][2][4][2];
    #pragma unroll
    for (int a = 0; a < 2; a++)
        #pragma unroll
        for (int b = 0; b < 2; b++)
            #pragma unroll
            for (int c = 0; c < 4; c++) { qg[a][b][c][0] = 0.f; qg[a][b][c][1] = 0.f; }

    const float kgelu = 0.70710678118654752f;

    // chunk loader: c = K-chunk (64 wide), bsel = stage, d = pass
    auto issue_chunk = [&](int d, int c, int bsel) {
        const int k0 = c * 64;
        const size_t colbase = (size_t)h * 4096 + (size_t)d * 64;
        char* astg = smraw + bsel * A_STG_BYTES;
        char* bstg = smraw + OFF_B + bsel * B_STG_BYTES;
        // A: 128 rows x 64 cols, hi+lo : per hilo 128*8 = 1024 CP16 -> it<4
        #pragma unroll
        for (int it = 0; it < 4; it++) {
            int idx = tid + it * 256;            // 0..1023
            int row = idx >> 3, seg = idx & 7;
            unsigned dsth = sptr(astg + row * (APAD * 2) + seg * 16);
            CP16CA(dsth, &g_x_hi[(size_t)(tok0 + row) * EMB + k0 + seg * 8]);
            CP16CA(dsth + A_HILO_BYTES, &g_x_lo[(size_t)(tok0 + row) * EMB + k0 + seg * 8]);
        }
        // B: 64 rows (k) x 64 cols (n): per hilo 64*8 = 512 CP16 -> it<2
        #pragma unroll
        for (int it = 0; it < 2; it++) {
            int idx = tid + it * 256;            // 0..511
            int row = idx >> 3, seg = idx & 7;   // 64 rows x 8 segs of 16B
            unsigned dsth = sptr(bstg + row * (APAD * 2) + seg * 16);
            CP16CG(dsth, &g_Wg_hi[(size_t)(k0 + row) * WGN + colbase + seg * 8]);
            CP16CG(dsth + B_HILO_BYTES, &g_Wg_lo[(size_t)(k0 + row) * WGN + colbase + seg * 8]);
        }
        asm volatile("cp.async.commit_group;\n");
    };

    issue_chunk(0, 0, 0);
    int bsel = 0;

    for (int d = 0; d < 64; d++) {
        float acc[2][4][4];
        #pragma unroll
        for (int a = 0; a < 2; a++)
            #pragma unroll
            for (int b = 0; b < 4; b++)
                #pragma unroll
                for (int cje = 0; cje < 4; cje++) acc[a][b][cje] = 0.f;

        for (int c = 0; c < 8; c++) {
            asm volatile("cp.async.wait_group 0;\n");
            __syncthreads();
            // prefetch next chunk (possibly next pass's first)
            if (c < 7)       issue_chunk(d, c + 1, bsel ^ 1);
            else if (d < 63) issue_chunk(d + 1, 0, bsel ^ 1);

            const __nv_bfloat16* Ab = (const __nv_bfloat16*)(smraw + bsel * A_STG_BYTES);
            const __nv_bfloat16* Bb = (const __nv_bfloat16*)(smraw + OFF_B + bsel * B_STG_BYTES);
            #pragma unroll
            for (int kk = 0; kk < 4; kk++) {
                unsigned Ah[2][4], Al[2][4], Bh[2][4], Bl[2][4];
                #pragma unroll
                for (int tm = 0; tm < 2; tm++) {
                    unsigned a = sptr(&Ab[(wm * 32 + tm * 16 + (lane & 15)) * APAD
                                          + kk * 16 + (lane >> 4) * 8]);
                    LDSM4(Ah[tm], a);
                    LDSM4(Al[tm], a + A_HILO_BYTES);
                }
                #pragma unroll
                for (int tn4 = 0; tn4 < 2; tn4++) {
                    unsigned b = sptr(&Bb[(kk * 16 + (lane & 15)) * APAD
                                          + wn * 32 + tn4 * 16 + (lane >> 4) * 8]);
                    LDSM4T(Bh[tn4], b);
                    LDSM4T(Bl[tn4], b + B_HILO_BYTES);
                }
                #pragma unroll
                for (int tm = 0; tm < 2; tm++)
                    #pragma unroll
                    for (int tn4 = 0; tn4 < 2; tn4++)
                        #pragma unroll
                        for (int hlf = 0; hlf < 2; hlf++) {
                            const int tn = tn4 * 2 + hlf;
                            MMA16816(acc[tm][tn], Ah[tm], Bh[tn4][hlf*2], Bh[tn4][hlf*2+1]);
                            MMA16816(acc[tm][tn], Ah[tm], Bl[tn4][hlf*2], Bl[tn4][hlf*2+1]);
                            MMA16816(acc[tm][tn], Al[tm], Bh[tn4][hlf*2], Bh[tn4][hlf*2+1]);
                        }
            }
            bsel ^= 1;
        }

        // Epilogue: bias + exact GELU + q-weighted accumulate into registers.
        #pragma unroll
        for (int tm = 0; tm < 2; tm++) {
            const int r0 = wm * 32 + tm * 16 + (lane >> 2);
            const float q0 = __ldg(&g_Q[(size_t)(tok0 + r0)     * EMB + h * 64 + d]);
            const float q1 = __ldg(&g_Q[(size_t)(tok0 + r0 + 8) * EMB + h * 64 + d]);
            #pragma unroll
            for (int tn = 0; tn < 4; tn++) {
                const int e = wn * 32 + tn * 8 + (lane & 3) * 2;
                const float b0 = __ldg(&bg[(size_t)h * 4096 + d * 64 + e]);
                const float b1 = __ldg(&bg[(size_t)h * 4096 + d * 64 + e + 1]);
                float s0 = acc[tm][tn][0] + b0;
                float s1 = acc[tm][tn][1] + b1;
                float s2 = acc[tm][tn][2] + b0;
                float s3 = acc[tm][tn][3] + b1;
                float g0 = 0.5f * s0 * (1.0f + erff(s0 * kgelu));
                float g1 = 0.5f * s1 * (1.0f + erff(s1 * kgelu));
                float g2 = 0.5f * s2 * (1.0f + erff(s2 * kgelu));
                float g3 = 0.5f * s3 * (1.0f + erff(s3 * kgelu));
                qg[tm][0][tn][0] = fmaf(q0, g0, qg[tm][0][tn][0]);
                qg[tm][0][tn][1] = fmaf(q0, g1, qg[tm][0][tn][1]);
                qg[tm][1][tn][0] = fmaf(q1, g2, qg[tm][1][tn][0]);
                qg[tm][1][tn][1] = fmaf(q1, g3, qg[tm][1][tn][1]);
            }
        }
    }

    // Direct store: each (row, e) owned by exactly one thread.
    #pragma unroll
    for (int tm = 0; tm < 2; tm++)
        #pragma unroll
        for (int rh = 0; rh < 2; rh++) {
            const int row = wm * 32 + tm * 16 + rh * 8 + (lane >> 2);
            #pragma unroll
            for (int tn = 0; tn < 4; tn++) {
                const int e = wn * 32 + tn * 8 + (lane & 3) * 2;
                float2 o = make_float2(qg[tm][rh][tn][0], qg[tm][rh][tn][1]);
                *(float2*)&g_QG[(size_t)(tok0 + row) * EMB + h * 64 + e] = o;
            }
        }
}

// ---------------------------------------------------------------------------
// Kernel 3: flash-style attention (unchanged)
// ---------------------------------------------------------------------------
__global__ __launch_bounds__(128) void attn_kernel(float* __restrict__ out)
{
    __shared__ float Ks[64 * 68];
    __shared__ float Vs[64 * 68];

    const int bh  = blockIdx.y;
    const int b   = bh >> 3;
    const int h   = bh & 7;
    const int tid = threadIdx.x;
    const int n   = blockIdx.x * 128 + tid;
    const size_t rowq = (size_t)(b * SEQ + n) * EMB + h * 64;

    float4 qgr[16], outr[16];
    #pragma unroll
    for (int i = 0; i < 16; i++) {
        qgr[i]  = *(const float4*)&g_QG[rowq + i * 4];
        outr[i] = make_float4(0.f, 0.f, 0.f, 0.f);
    }
    float m = -INFINITY, l = 0.f;

    for (int kb = 0; kb < 16; kb++) {
        __syncthreads();
        #pragma unroll
        for (int it = 0; it < 8; it++) {
            int idx = tid + it * 128;
            int r   = idx >> 4;
            int c4  = (idx & 15) << 2;
            size_t g = (size_t)(b * SEQ + kb * 64 + r) * EMB + h * 64 + c4;
            *(float4*)&Ks[r * 68 + c4] = *(const float4*)&g_K[g];
            *(float4*)&Vs[r * 68 + c4] = *(const float4*)&g_V[g];
        }
        __syncthreads();

        #pragma unroll 1
        for (int j0 = 0; j0 < 64; j0 += 8) {
            float s[8];
            #pragma unroll
            for (int jj = 0; jj < 8; jj++) {
                const float* kr = &Ks[(j0 + jj) * 68];
                float a = 0.f;
                #pragma unroll
                for (int e = 0; e < 16; e++) {
                    float4 kv = *(const float4*)&kr[e * 4];
                    a = fmaf(qgr[e].x, kv.x, a);
                    a = fmaf(qgr[e].y, kv.y, a);
                    a = fmaf(qgr[e].z, kv.z, a);
                    a = fmaf(qgr[e].w, kv.w, a);
                }
                s[jj] = a;
            }
            float cmax = s[0];
            #pragma unroll
            for (int jj = 1; jj < 8; jj++) cmax = fmaxf(cmax, s[jj]);
            float mnew = fmaxf(m, cmax);
            float corr = __expf(m - mnew);
            l *= corr;
            #pragma unroll
            for (int i = 0; i < 16; i++) {
                outr[i].x *= corr; outr[i].y *= corr;
                outr[i].z *= corr; outr[i].w *= corr;
            }
            #pragma unroll
            for (int jj = 0; jj < 8; jj++) {
                float p = __expf(s[jj] - mnew);
                l += p;
                const float* vr = &Vs[(j0 + jj) * 68];
                #pragma unroll
                for (int i = 0; i < 16; i++) {
                    float4 vv = *(const float4*)&vr[i * 4];
                    outr[i].x = fmaf(p, vv.x, outr[i].x);
                    outr[i].y = fmaf(p, vv.y, outr[i].y);
                    outr[i].z = fmaf(p, vv.z, outr[i].z);
                    outr[i].w = fmaf(p, vv.w, outr[i].w);
                }
            }
            m = mnew;
        }
    }

    const float inv = 1.0f / l;
    #pragma unroll
    for (int i = 0; i < 16; i++) {
        float4 o = make_float4(outr[i].x * inv, outr[i].y * inv,
                               outr[i].z * inv, outr[i].w * inv);
        *(float4*)&out[rowq + i * 4] = o;
    }
}

// ---------------------------------------------------------------------------
extern "C" void kernel_launch(void* const* d_in, const int* in_sizes, int n_in,
                              void* d_out, int out_size)
{
    const float* x  = (const float*)d_in[0];
    const float* Wq = (const float*)d_in[1];
    const float* bq = (const float*)d_in[2];
    const float* Wk = (const float*)d_in[3];
    const float* bk = (const float*)d_in[4];
    const float* Wv = (const float*)d_in[5];
    const float* bv = (const float*)d_in[6];
    const float* Wg = (const float*)d_in[7];
    const float* bg = (const float*)d_in[8];
    float* out = (float*)d_out;

    __nv_bfloat16 *xhi, *xlo, *whi, *wlo;
    cudaGetSymbolAddress((void**)&xhi, g_x_hi);
    cudaGetSymbolAddress((void**)&xlo, g_x_lo);
    cudaGetSymbolAddress((void**)&whi, g_Wg_hi);
    cudaGetSymbolAddress((void**)&wlo, g_Wg_lo);

    {   // split x
        int n4 = TOK * EMB / 4;
        split_kernel<<<(n4 + 255) / 256, 256>>>(x, xhi, xlo, n4);
    }
    {   // split Wg (kept K-major [K, N])
        int n4 = EMB * WGN / 4;
        split_kernel<<<(n4 + 255) / 256, 256>>>(Wg, whi, wlo, n4);
    }

    dim3 g1(TOK / 64, EMB / 64, 3);
    qkv_kernel<<<g1, 256>>>(x, Wq, bq, Wk, bk, Wv, bv);

    cudaFuncSetAttribute(qg_mma_kernel, cudaFuncAttributeMaxDynamicSharedMemorySize, QG_SMEM);
    dim3 g2(TOK / 128, HEADS);
    qg_mma_kernel<<<g2, 256, QG_SMEM>>>(bg);

    dim3 g3(SEQ / 128, BATCH * HEADS);
    attn_kernel<<<g3, 128>>>(out);
}

// round 11
// speedup vs baseline: 3.0902x; 1.0103x over previous
#include <cuda_runtime.h>
#include <cuda_bf16.h>
#include <math.h>

#define BATCH 4
#define SEQ   1024
#define EMB   512
#define HEADS 8
#define HD    64
#define TOK   (BATCH*SEQ)     // 4096
#define WGN   32768

// Scratch (device globals; no allocations allowed)
__device__ float g_Q [TOK*EMB];
__device__ float g_K [TOK*EMB];
__device__ float g_V [TOK*EMB];
__device__ float g_QG[TOK*EMB];
__device__ __align__(16) __nv_bfloat16 g_x_hi [TOK*EMB];
__device__ __align__(16) __nv_bfloat16 g_x_lo [TOK*EMB];
__device__ __align__(16) __nv_bfloat16 g_Wg_hi[(size_t)EMB*WGN];
__device__ __align__(16) __nv_bfloat16 g_Wg_lo[(size_t)EMB*WGN];

__device__ __forceinline__ unsigned sptr(const void* p) {
    return (unsigned)__cvta_generic_to_shared(p);
}

#define CP16CG(dst, src) \
    asm volatile("cp.async.cg.shared.global [%0], [%1], 16;\n" :: "r"(dst), "l"(src))

#define LDSM4(R, addr) \
    asm volatile("ldmatrix.sync.aligned.m8n8.x4.shared.b16 {%0,%1,%2,%3}, [%4];\n" \
        : "=r"((R)[0]), "=r"((R)[1]), "=r"((R)[2]), "=r"((R)[3]) : "r"(addr))

#define LDSM4T(R, addr) \
    asm volatile("ldmatrix.sync.aligned.m8n8.x4.trans.shared.b16 {%0,%1,%2,%3}, [%4];\n" \
        : "=r"((R)[0]), "=r"((R)[1]), "=r"((R)[2]), "=r"((R)[3]) : "r"(addr))

#define MMA16816(C, A, b0, b1) \
    asm volatile("mma.sync.aligned.m16n8k16.row.col.f32.bf16.bf16.f32 " \
        "{%0,%1,%2,%3}, {%4,%5,%6,%7}, {%8,%9}, {%0,%1,%2,%3};\n" \
        : "+f"((C)[0]), "+f"((C)[1]), "+f"((C)[2]), "+f"((C)[3]) \
        : "r"((A)[0]), "r"((A)[1]), "r"((A)[2]), "r"((A)[3]), "r"(b0), "r"(b1))

// ---------------------------------------------------------------------------
// Split fp32 -> bf16 hi + bf16 lo
// ---------------------------------------------------------------------------
__global__ void split_kernel(const float* __restrict__ src,
                             __nv_bfloat16* __restrict__ hi,
                             __nv_bfloat16* __restrict__ lo, int n4)
{
    int i = blockIdx.x * blockDim.x + threadIdx.x;
    if (i >= n4) return;
    float4 v = ((const float4*)src)[i];
    float vv[4] = {v.x, v.y, v.z, v.w};
    __nv_bfloat16 h4[4], l4[4];
    #pragma unroll
    for (int j = 0; j < 4; j++) {
        __nv_bfloat16 hh = __float2bfloat16(vv[j]);
        h4[j] = hh;
        l4[j] = __float2bfloat16(vv[j] - __bfloat162float(hh));
    }
    *(uint2*)(hi + 4 * (size_t)i) = *(uint2*)h4;
    *(uint2*)(lo + 4 * (size_t)i) = *(uint2*)l4;
}

// ---------------------------------------------------------------------------
// Kernel 1: QKV projections (unchanged)
// ---------------------------------------------------------------------------
__global__ __launch_bounds__(256) void qkv_kernel(
    const float* __restrict__ x,
    const float* __restrict__ Wq, const float* __restrict__ bq,
    const float* __restrict__ Wk, const float* __restrict__ bk,
    const float* __restrict__ Wv, const float* __restrict__ bv)
{
    const int which = blockIdx.z;
    const float* Wm = (which == 0) ? Wq : (which == 1) ? Wk : Wv;
    const float* bm = (which == 0) ? bq : (which == 1) ? bk : bv;
    float* outp     = (which == 0) ? g_Q : (which == 1) ? g_K : g_V;

    __shared__ float As[64 * 20];
    __shared__ float Bs[16 * 68];

    const int tid = threadIdx.x;
    const int tx  = tid & 15;
    const int ty  = tid >> 4;
    const int m0  = blockIdx.x * 64;
    const int n0  = blockIdx.y * 64;

    float acc[4][4] = {};

    for (int k0 = 0; k0 < EMB; k0 += 16) {
        __syncthreads();
        {
            int t  = tid >> 2;
            int c4 = (tid & 3) << 2;
            float4 v = *(const float4*)&x[(size_t)(m0 + t) * EMB + k0 + c4];
            *(float4*)&As[t * 20 + c4] = v;
            int r  = tid >> 4;
            int cc = (tid & 15) << 2;
            float4 w = *(const float4*)&Wm[(size_t)(k0 + r) * EMB + n0 + cc];
            *(float4*)&Bs[r * 68 + cc] = w;
        }
        __syncthreads();
        #pragma unroll
        for (int kk = 0; kk < 16; kk++) {
            float4 w = *(const float4*)&Bs[kk * 68 + tx * 4];
            #pragma unroll
            for (int i = 0; i < 4; i++) {
                float a = As[(ty * 4 + i) * 20 + kk];
                acc[i][0] = fmaf(a, w.x, acc[i][0]);
                acc[i][1] = fmaf(a, w.y, acc[i][1]);
                acc[i][2] = fmaf(a, w.z, acc[i][2]);
                acc[i][3] = fmaf(a, w.w, acc[i][3]);
            }
        }
    }

    const float4 bb = *(const float4*)&bm[n0 + tx * 4];
    #pragma unroll
    for (int i = 0; i < 4; i++) {
        float4 o = make_float4(acc[i][0] + bb.x, acc[i][1] + bb.y,
                               acc[i][2] + bb.z, acc[i][3] + bb.w);
        *(float4*)&outp[(size_t)(m0 + ty * 4 + i) * EMB + n0 + tx * 4] = o;
    }
}

// ---------------------------------------------------------------------------
// Kernel 2 (dominant): HMMA fused  g = gelu(x@Wg+bg), qg = sum_d q_d * g_d
// CTA = 128 tokens x 1 head, 256 threads, 2 CTAs/SM (grid 256 = one wave).
// 32 passes of N=128 (a d-PAIR); e-split: N-warp wn owns e in
// [wn*32, wn*32+32) of BOTH d's (S cols wn*32..+31 and 64+wn*32..+31).
// -> each (row,e) owned by ONE thread all kernel; both d's fold into one
// race-free SMEM qg buffer. K=512 in 16 double-buffered 32-wide chunks.
// bf16 hi/lo 3-product split, fp32 accumulate.
// SMEM: A 2stg x 2hilo x 128x40 bf16 (40960) | B 2stg x 2hilo x 32x136
// (34816) | qg 128x66 f32 (33792)  = 109568 bytes -> x2 CTAs = 219136.
// ---------------------------------------------------------------------------
#define A_HILO 10240                  // 128*40*2
#define A_STG  20480
#define B_HILO 8704                   // 32*136*2
#define B_STG  17408
#define OFF_B  40960
#define OFF_QG 75776
#define QG_SMEM 109568

__global__ __launch_bounds__(256, 2) void qg_mma_kernel(const float* __restrict__ bg)
{
    extern __shared__ char smraw[];
    float* qgs = (float*)(smraw + OFF_QG);   // [128][66]

    const int tid  = threadIdx.x;
    const int lane = tid & 31;
    const int w    = tid >> 5;
    const int wm   = w & 3;        // M warp (32 rows)
    const int wn   = w >> 2;       // e-half owner (32 e-cols, both d's)
    const int h    = blockIdx.y;
    const int tok0 = blockIdx.x * 128;

    // zero qg accumulator
    for (int i = tid; i < 128 * 66 / 2; i += 256)
        *(float2*)&qgs[i * 2] = make_float2(0.f, 0.f);
    // (sync below, before first compute)

    const float kgelu = 0.70710678118654752f;

    // chunk loader: p = pass (d-pair), c = K-chunk (32 wide), bsel = stage
    auto issue_chunk = [&](int p, int c, int bsel) {
        const int k0 = c * 32;
        const size_t colbase = (size_t)h * 4096 + (size_t)p * 128;
        char* astg = smraw + bsel * A_STG;
        char* bstg = smraw + OFF_B + bsel * B_STG;
        // A: 128 rows x 32 cols (4 segs of 8 bf16), hi+lo
        #pragma unroll
        for (int it = 0; it < 2; it++) {
            int idx = tid + it * 256;            // 0..511
            int row = idx >> 2, seg = idx & 3;
            unsigned dst = sptr(astg + row * 80 + seg * 16);
            CP16CG(dst,          &g_x_hi[(size_t)(tok0 + row) * EMB + k0 + seg * 8]);
            CP16CG(dst + A_HILO, &g_x_lo[(size_t)(tok0 + row) * EMB + k0 + seg * 8]);
        }
        // B: 32 k-rows x 128 n-cols (16 segs of 8 bf16), hi+lo
        #pragma unroll
        for (int it = 0; it < 2; it++) {
            int idx = tid + it * 256;            // 0..511
            int row = idx >> 4, seg = idx & 15;
            unsigned dst = sptr(bstg + row * 272 + seg * 16);
            CP16CG(dst,          &g_Wg_hi[(size_t)(k0 + row) * WGN + colbase + seg * 8]);
            CP16CG(dst + B_HILO, &g_Wg_lo[(size_t)(k0 + row) * WGN + colbase + seg * 8]);
        }
        asm volatile("cp.async.commit_group;\n");
    };

    issue_chunk(0, 0, 0);
    int bsel = 0;

    for (int p = 0; p < 32; p++) {
        float acc[2][8][4];
        #pragma unroll
        for (int a = 0; a < 2; a++)
            #pragma unroll
            for (int b = 0; b < 8; b++)
                #pragma unroll
                for (int cj = 0; cj < 4; cj++) acc[a][b][cj] = 0.f;

        for (int c = 0; c < 16; c++) {
            asm volatile("cp.async.wait_group 0;\n");
            __syncthreads();
            if (c < 15)      issue_chunk(p, c + 1, bsel ^ 1);
            else if (p < 31) issue_chunk(p + 1, 0, bsel ^ 1);

            const char* Ab = smraw + bsel * A_STG;
            const char* Bb = smraw + OFF_B + bsel * B_STG;
            #pragma unroll
            for (int kk = 0; kk < 2; kk++) {
                unsigned Ah[2][4], Al[2][4];
                #pragma unroll
                for (int tm = 0; tm < 2; tm++) {
                    unsigned a = sptr(Ab + (wm * 32 + tm * 16 + (lane & 15)) * 80
                                      + kk * 32 + (lane >> 4) * 16);
                    LDSM4(Ah[tm], a);
                    LDSM4(Al[tm], a + A_HILO);
                }
                #pragma unroll
                for (int g = 0; g < 4; g++) {
                    unsigned Bh[4], Bl[4];
                    const int n0 = (g >> 1) * 64 + wn * 32 + (g & 1) * 16;
                    unsigned b = sptr(Bb + (kk * 16 + (lane & 15)) * 272
                                      + (n0 + (lane >> 4) * 8) * 2);
                    LDSM4T(Bh, b);
                    LDSM4T(Bl, b + B_HILO);
                    #pragma unroll
                    for (int tm = 0; tm < 2; tm++)
                        #pragma unroll
                        for (int hlf = 0; hlf < 2; hlf++) {
                            const int tn = g * 2 + hlf;
                            MMA16816(acc[tm][tn], Ah[tm], Bh[hlf*2], Bh[hlf*2+1]);
                            MMA16816(acc[tm][tn], Ah[tm], Bl[hlf*2], Bl[hlf*2+1]);
                            MMA16816(acc[tm][tn], Al[tm], Bh[hlf*2], Bh[hlf*2+1]);
                        }
                }
            }
            bsel ^= 1;
        }

        // Epilogue: bias + exact GELU + q-weighted fold of the d-pair into qg.
        const int d0 = 2 * p, d1 = d0 + 1;
        #pragma unroll
        for (int tm = 0; tm < 2; tm++) {
            const int r0 = wm * 32 + tm * 16 + (lane >> 2);
            const int r1 = r0 + 8;
            const float q00 = __ldg(&g_Q[(size_t)(tok0 + r0) * EMB + h * 64 + d0]);
            const float q01 = __ldg(&g_Q[(size_t)(tok0 + r0) * EMB + h * 64 + d1]);
            const float q10 = __ldg(&g_Q[(size_t)(tok0 + r1) * EMB + h * 64 + d0]);
            const float q11 = __ldg(&g_Q[(size_t)(tok0 + r1) * EMB + h * 64 + d1]);
            #pragma unroll
            for (int eg = 0; eg < 2; eg++)
                #pragma unroll
                for (int hlf = 0; hlf < 2; hlf++) {
                    const int tnA = eg * 2 + hlf;       // d0 tile
                    const int tnB = tnA + 4;            // d1 tile
                    const int e = wn * 32 + eg * 16 + hlf * 8 + (lane & 3) * 2;
                    const float bA0 = __ldg(&bg[(size_t)h * 4096 + d0 * 64 + e]);
                    const float bA1 = __ldg(&bg[(size_t)h * 4096 + d0 * 64 + e + 1]);
                    const float bB0 = __ldg(&bg[(size_t)h * 4096 + d1 * 64 + e]);
                    const float bB1 = __ldg(&bg[(size_t)h * 4096 + d1 * 64 + e + 1]);
                    float sA0 = acc[tm][tnA][0] + bA0, sA1 = acc[tm][tnA][1] + bA1;
                    float sA2 = acc[tm][tnA][2] + bA0, sA3 = acc[tm][tnA][3] + bA1;
                    float sB0 = acc[tm][tnB][0] + bB0, sB1 = acc[tm][tnB][1] + bB1;
                    float sB2 = acc[tm][tnB][2] + bB0, sB3 = acc[tm][tnB][3] + bB1;
                    float gA0 = 0.5f * sA0 * (1.0f + erff(sA0 * kgelu));
                    float gA1 = 0.5f * sA1 * (1.0f + erff(sA1 * kgelu));
                    float gA2 = 0.5f * sA2 * (1.0f + erff(sA2 * kgelu));
                    float gA3 = 0.5f * sA3 * (1.0f + erff(sA3 * kgelu));
                    float gB0 = 0.5f * sB0 * (1.0f + erff(sB0 * kgelu));
                    float gB1 = 0.5f * sB1 * (1.0f + erff(sB1 * kgelu));
                    float gB2 = 0.5f * sB2 * (1.0f + erff(sB2 * kgelu));
                    float gB3 = 0.5f * sB3 * (1.0f + erff(sB3 * kgelu));
                    float2* p0 = (float2*)&qgs[r0 * 66 + e];
                    float2* p1 = (float2*)&qgs[r1 * 66 + e];
                    float2 v0 = *p0, v1 = *p1;
                    v0.x += q00 * gA0 + q01 * gB0;
                    v0.y += q00 * gA1 + q01 * gB1;
                    v1.x += q10 * gA2 + q11 * gB2;
                    v1.y += q10 * gA3 + q11 * gB3;
                    *p0 = v0; *p1 = v1;
                }
        }
    }

    // Final store: each (row, e) slot owned by this thread.
    #pragma unroll
    for (int tm = 0; tm < 2; tm++)
        #pragma unroll
        for (int rh = 0; rh < 2; rh++) {
            const int row = wm * 32 + tm * 16 + rh * 8 + (lane >> 2);
            #pragma unroll
            for (int eg = 0; eg < 2; eg++)
                #pragma unroll
                for (int hlf = 0; hlf < 2; hlf++) {
                    const int e = wn * 32 + eg * 16 + hlf * 8 + (lane & 3) * 2;
                    float2 v = *(float2*)&qgs[row * 66 + e];
                    *(float2*)&g_QG[(size_t)(tok0 + row) * EMB + h * 64 + e] = v;
                }
        }
}

// ---------------------------------------------------------------------------
// Kernel 3: flash-style attention (unchanged)
// ---------------------------------------------------------------------------
__global__ __launch_bounds__(128) void attn_kernel(float* __restrict__ out)
{
    __shared__ float Ks[64 * 68];
    __shared__ float Vs[64 * 68];

    const int bh  = blockIdx.y;
    const int b   = bh >> 3;
    const int h   = bh & 7;
    const int tid = threadIdx.x;
    const int n   = blockIdx.x * 128 + tid;
    const size_t rowq = (size_t)(b * SEQ + n) * EMB + h * 64;

    float4 qgr[16], outr[16];
    #pragma unroll
    for (int i = 0; i < 16; i++) {
        qgr[i]  = *(const float4*)&g_QG[rowq + i * 4];
        outr[i] = make_float4(0.f, 0.f, 0.f, 0.f);
    }
    float m = -INFINITY, l = 0.f;

    for (int kb = 0; kb < 16; kb++) {
        __syncthreads();
        #pragma unroll
        for (int it = 0; it < 8; it++) {
            int idx = tid + it * 128;
            int r   = idx >> 4;
            int c4  = (idx & 15) << 2;
            size_t g = (size_t)(b * SEQ + kb * 64 + r) * EMB + h * 64 + c4;
            *(float4*)&Ks[r * 68 + c4] = *(const float4*)&g_K[g];
            *(float4*)&Vs[r * 68 + c4] = *(const float4*)&g_V[g];
        }
        __syncthreads();

        #pragma unroll 1
        for (int j0 = 0; j0 < 64; j0 += 8) {
            float s[8];
            #pragma unroll
            for (int jj = 0; jj < 8; jj++) {
                const float* kr = &Ks[(j0 + jj) * 68];
                float a = 0.f;
                #pragma unroll
                for (int e = 0; e < 16; e++) {
                    float4 kv = *(const float4*)&kr[e * 4];
                    a = fmaf(qgr[e].x, kv.x, a);
                    a = fmaf(qgr[e].y, kv.y, a);
                    a = fmaf(qgr[e].z, kv.z, a);
                    a = fmaf(qgr[e].w, kv.w, a);
                }
                s[jj] = a;
            }
            float cmax = s[0];
            #pragma unroll
            for (int jj = 1; jj < 8; jj++) cmax = fmaxf(cmax, s[jj]);
            float mnew = fmaxf(m, cmax);
            float corr = __expf(m - mnew);
            l *= corr;
            #pragma unroll
            for (int i = 0; i < 16; i++) {
                outr[i].x *= corr; outr[i].y *= corr;
                outr[i].z *= corr; outr[i].w *= corr;
            }
            #pragma unroll
            for (int jj = 0; jj < 8; jj++) {
                float p = __expf(s[jj] - mnew);
                l += p;
                const float* vr = &Vs[(j0 + jj) * 68];
                #pragma unroll
                for (int i = 0; i < 16; i++) {
                    float4 vv = *(const float4*)&vr[i * 4];
                    outr[i].x = fmaf(p, vv.x, outr[i].x);
                    outr[i].y = fmaf(p, vv.y, outr[i].y);
                    outr[i].z = fmaf(p, vv.z, outr[i].z);
                    outr[i].w = fmaf(p, vv.w, outr[i].w);
                }
            }
            m = mnew;
        }
    }

    const float inv = 1.0f / l;
    #pragma unroll
    for (int i = 0; i < 16; i++) {
        float4 o = make_float4(outr[i].x * inv, outr[i].y * inv,
                               outr[i].z * inv, outr[i].w * inv);
        *(float4*)&out[rowq + i * 4] = o;
    }
}

// ---------------------------------------------------------------------------
extern "C" void kernel_launch(void* const* d_in, const int* in_sizes, int n_in,
                              void* d_out, int out_size)
{
    const float* x  = (const float*)d_in[0];
    const float* Wq = (const float*)d_in[1];
    const float* bq = (const float*)d_in[2];
    const float* Wk = (const float*)d_in[3];
    const float* bk = (const float*)d_in[4];
    const float* Wv = (const float*)d_in[5];
    const float* bv = (const float*)d_in[6];
    const float* Wg = (const float*)d_in[7];
    const float* bg = (const float*)d_in[8];
    float* out = (float*)d_out;

    __nv_bfloat16 *xhi, *xlo, *whi, *wlo;
    cudaGetSymbolAddress((void**)&xhi, g_x_hi);
    cudaGetSymbolAddress((void**)&xlo, g_x_lo);
    cudaGetSymbolAddress((void**)&whi, g_Wg_hi);
    cudaGetSymbolAddress((void**)&wlo, g_Wg_lo);

    {   // split x
        int n4 = TOK * EMB / 4;
        split_kernel<<<(n4 + 255) / 256, 256>>>(x, xhi, xlo, n4);
    }
    {   // split Wg (kept K-major [K, N])
        int n4 = EMB * WGN / 4;
        split_kernel<<<(n4 + 255) / 256, 256>>>(Wg, whi, wlo, n4);
    }

    dim3 g1(TOK / 64, EMB / 64, 3);
    qkv_kernel<<<g1, 256>>>(x, Wq, bq, Wk, bk, Wv, bv);

    cudaFuncSetAttribute(qg_mma_kernel, cudaFuncAttributeMaxDynamicSharedMemorySize, QG_SMEM);
    dim3 g2(TOK / 128, HEADS);
    qg_mma_kernel<<<g2, 256, QG_SMEM>>>(bg);

    dim3 g3(SEQ / 128, BATCH * HEADS);
    attn_kernel<<<g3, 128>>>(out);
}

// round 13
// speedup vs baseline: 3.6938x; 1.1953x over previous
#include <cuda_runtime.h>
#include <cuda_bf16.h>
#include <cuda_fp16.h>
#include <math.h>

#define BATCH 4
#define SEQ   1024
#define EMB   512
#define HEADS 8
#define HD    64
#define TOK   (BATCH*SEQ)     // 4096
#define WGN   32768

// Scratch (device globals; no allocations allowed)
__device__ float g_Q [TOK*EMB];
__device__ float g_K [TOK*EMB];
__device__ float g_V [TOK*EMB];
__device__ float g_QG[TOK*EMB];
__device__ __align__(16) __half g_x_h16 [TOK*EMB];
__device__ __align__(16) __half g_x_l16 [TOK*EMB];
__device__ __align__(16) __half g_Wg_h16[(size_t)EMB*WGN];

__device__ __forceinline__ unsigned sptr(const void* p) {
    return (unsigned)__cvta_generic_to_shared(p);
}

#define CP16CG(dst, src) \
    asm volatile("cp.async.cg.shared.global [%0], [%1], 16;\n" :: "r"(dst), "l"(src))

#define LDSM4(R, addr) \
    asm volatile("ldmatrix.sync.aligned.m8n8.x4.shared.b16 {%0,%1,%2,%3}, [%4];\n" \
        : "=r"((R)[0]), "=r"((R)[1]), "=r"((R)[2]), "=r"((R)[3]) : "r"(addr))

#define LDSM4T(R, addr) \
    asm volatile("ldmatrix.sync.aligned.m8n8.x4.trans.shared.b16 {%0,%1,%2,%3}, [%4];\n" \
        : "=r"((R)[0]), "=r"((R)[1]), "=r"((R)[2]), "=r"((R)[3]) : "r"(addr))

#define MMA16816F(C, A, b0, b1) \
    asm volatile("mma.sync.aligned.m16n8k16.row.col.f32.f16.f16.f32 " \
        "{%0,%1,%2,%3}, {%4,%5,%6,%7}, {%8,%9}, {%0,%1,%2,%3};\n" \
        : "+f"((C)[0]), "+f"((C)[1]), "+f"((C)[2]), "+f"((C)[3]) \
        : "r"((A)[0]), "r"((A)[1]), "r"((A)[2]), "r"((A)[3]), "r"(b0), "r"(b1))

// ---------------------------------------------------------------------------
// x: fp32 -> fp16 hi + fp16 lo (hi+lo captures ~22 mantissa bits)
// ---------------------------------------------------------------------------
__global__ void split2_fp16_kernel(const float* __restrict__ src,
                                   __half* __restrict__ hi,
                                   __half* __restrict__ lo, int n4)
{
    int i = blockIdx.x * blockDim.x + threadIdx.x;
    if (i >= n4) return;
    float4 v = ((const float4*)src)[i];
    float vv[4] = {v.x, v.y, v.z, v.w};
    __half h4[4], l4[4];
    #pragma unroll
    for (int j = 0; j < 4; j++) {
        __half hh = __float2half_rn(vv[j]);
        h4[j] = hh;
        l4[j] = __float2half_rn(vv[j] - __half2float(hh));
    }
    *(uint2*)(hi + 4 * (size_t)i) = *(uint2*)h4;
    *(uint2*)(lo + 4 * (size_t)i) = *(uint2*)l4;
}

// Wg: fp32 -> single fp16
__global__ void cast_fp16_kernel(const float* __restrict__ src,
                                 __half* __restrict__ dst, int n4)
{
    int i = blockIdx.x * blockDim.x + threadIdx.x;
    if (i >= n4) return;
    float4 v = ((const float4*)src)[i];
    __half h4[4] = { __float2half_rn(v.x), __float2half_rn(v.y),
                     __float2half_rn(v.z), __float2half_rn(v.w) };
    *(uint2*)(dst + 4 * (size_t)i) = *(uint2*)h4;
}

// ---------------------------------------------------------------------------
// Kernel 1: QKV projections (unchanged)
// ---------------------------------------------------------------------------
__global__ __launch_bounds__(256) void qkv_kernel(
    const float* __restrict__ x,
    const float* __restrict__ Wq, const float* __restrict__ bq,
    const float* __restrict__ Wk, const float* __restrict__ bk,
    const float* __restrict__ Wv, const float* __restrict__ bv)
{
    const int which = blockIdx.z;
    const float* Wm = (which == 0) ? Wq : (which == 1) ? Wk : Wv;
    const float* bm = (which == 0) ? bq : (which == 1) ? bk : bv;
    float* outp     = (which == 0) ? g_Q : (which == 1) ? g_K : g_V;

    __shared__ float As[64 * 20];
    __shared__ float Bs[16 * 68];

    const int tid = threadIdx.x;
    const int tx  = tid & 15;
    const int ty  = tid >> 4;
    const int m0  = blockIdx.x * 64;
    const int n0  = blockIdx.y * 64;

    float acc[4][4] = {};

    for (int k0 = 0; k0 < EMB; k0 += 16) {
        __syncthreads();
        {
            int t  = tid >> 2;
            int c4 = (tid & 3) << 2;
            float4 v = *(const float4*)&x[(size_t)(m0 + t) * EMB + k0 + c4];
            *(float4*)&As[t * 20 + c4] = v;
            int r  = tid >> 4;
            int cc = (tid & 15) << 2;
            float4 w = *(const float4*)&Wm[(size_t)(k0 + r) * EMB + n0 + cc];
            *(float4*)&Bs[r * 68 + cc] = w;
        }
        __syncthreads();
        #pragma unroll
        for (int kk = 0; kk < 16; kk++) {
            float4 w = *(const float4*)&Bs[kk * 68 + tx * 4];
            #pragma unroll
            for (int i = 0; i < 4; i++) {
                float a = As[(ty * 4 + i) * 20 + kk];
                acc[i][0] = fmaf(a, w.x, acc[i][0]);
                acc[i][1] = fmaf(a, w.y, acc[i][1]);
                acc[i][2] = fmaf(a, w.z, acc[i][2]);
                acc[i][3] = fmaf(a, w.w, acc[i][3]);
            }
        }
    }

    const float4 bb = *(const float4*)&bm[n0 + tx * 4];
    #pragma unroll
    for (int i = 0; i < 4; i++) {
        float4 o = make_float4(acc[i][0] + bb.x, acc[i][1] + bb.y,
                               acc[i][2] + bb.z, acc[i][3] + bb.w);
        *(float4*)&outp[(size_t)(m0 + ty * 4 + i) * EMB + n0 + tx * 4] = o;
    }
}

// ---------------------------------------------------------------------------
// Kernel 2 (dominant): HMMA fused  g = gelu(x@Wg+bg), qg = sum_d q_d * g_d
// fp16 2-product split:  x = xh + xl (fp16 exact),  W as single fp16:
//   x@W ~= xh@Wh + xl@Wh   (error = x@(W - Wh) ~ 1.6e-4 relative in s)
// CTA = 128 tokens x 1 head, 256 threads, 2 CTAs/SM (grid 256 = one wave).
// 32 passes of N=128 (a d-PAIR); e-split: N-warp wn owns e in
// [wn*32, wn*32+32) of BOTH d's -> each (row,e) owned by ONE thread; both
// d's fold into one race-free SMEM qg buffer. K=512 in 16 double-buffered
// 32-wide chunks.
// SMEM: A 2stg x 2hilo x 128x40 half (40960) | B 2stg x 32x136 half (17408)
//       | qg 128x66 f32 (33792)  = 92160 bytes -> x2 CTAs = 184320.
// ---------------------------------------------------------------------------
#define A_HILO 10240                  // 128*40*2
#define A_STG  20480
#define B_STG  8704                   // 32*136*2
#define OFF_B  40960
#define OFF_QG 58368
#define QG_SMEM 92160

__global__ __launch_bounds__(256, 2) void qg_mma_kernel(const float* __restrict__ bg)
{
    extern __shared__ char smraw[];
    float* qgs = (float*)(smraw + OFF_QG);   // [128][66]

    const int tid  = threadIdx.x;
    const int lane = tid & 31;
    const int w    = tid >> 5;
    const int wm   = w & 3;        // M warp (32 rows)
    const int wn   = w >> 2;       // e-half owner (32 e-cols, both d's)
    const int h    = blockIdx.y;
    const int tok0 = blockIdx.x * 128;

    // zero qg accumulator
    for (int i = tid; i < 128 * 66 / 2; i += 256)
        *(float2*)&qgs[i * 2] = make_float2(0.f, 0.f);

    const float kgelu = 0.70710678118654752f;

    // chunk loader: p = pass (d-pair), c = K-chunk (32 wide), bsel = stage
    auto issue_chunk = [&](int p, int c, int bsel) {
        const int k0 = c * 32;
        const size_t colbase = (size_t)h * 4096 + (size_t)p * 128;
        char* astg = smraw + bsel * A_STG;
        char* bstg = smraw + OFF_B + bsel * B_STG;
        // A: 128 rows x 32 cols (4 segs of 8 half), hi+lo
        #pragma unroll
        for (int it = 0; it < 2; it++) {
            int idx = tid + it * 256;            // 0..511
            int row = idx >> 2, seg = idx & 3;
            unsigned dst = sptr(astg + row * 80 + seg * 16);
            CP16CG(dst,          &g_x_h16[(size_t)(tok0 + row) * EMB + k0 + seg * 8]);
            CP16CG(dst + A_HILO, &g_x_l16[(size_t)(tok0 + row) * EMB + k0 + seg * 8]);
        }
        // B: 32 k-rows x 128 n-cols (16 segs of 8 half), single precision level
        #pragma unroll
        for (int it = 0; it < 2; it++) {
            int idx = tid + it * 256;            // 0..511
            int row = idx >> 4, seg = idx & 15;
            unsigned dst = sptr(bstg + row * 272 + seg * 16);
            CP16CG(dst, &g_Wg_h16[(size_t)(k0 + row) * WGN + colbase + seg * 8]);
        }
        asm volatile("cp.async.commit_group;\n");
    };

    issue_chunk(0, 0, 0);
    int bsel = 0;

    for (int p = 0; p < 32; p++) {
        float acc[2][8][4];
        #pragma unroll
        for (int a = 0; a < 2; a++)
            #pragma unroll
            for (int b = 0; b < 8; b++)
                #pragma unroll
                for (int cj = 0; cj < 4; cj++) acc[a][b][cj] = 0.f;

        for (int c = 0; c < 16; c++) {
            asm volatile("cp.async.wait_group 0;\n");
            __syncthreads();
            if (c < 15)      issue_chunk(p, c + 1, bsel ^ 1);
            else if (p < 31) issue_chunk(p + 1, 0, bsel ^ 1);

            const char* Ab = smraw + bsel * A_STG;
            const char* Bb = smraw + OFF_B + bsel * B_STG;
            #pragma unroll
            for (int kk = 0; kk < 2; kk++) {
                unsigned Ah[2][4], Al[2][4];
                #pragma unroll
                for (int tm = 0; tm < 2; tm++) {
                    unsigned a = sptr(Ab + (wm * 32 + tm * 16 + (lane & 15)) * 80
                                      + kk * 32 + (lane >> 4) * 16);
                    LDSM4(Ah[tm], a);
                    LDSM4(Al[tm], a + A_HILO);
                }
                #pragma unroll
                for (int g = 0; g < 4; g++) {
                    unsigned Bh[4];
                    const int n0 = (g >> 1) * 64 + wn * 32 + (g & 1) * 16;
                    unsigned b = sptr(Bb + (kk * 16 + (lane & 15)) * 272
                                      + (n0 + (lane >> 4) * 8) * 2);
                    LDSM4T(Bh, b);
                    #pragma unroll
                    for (int tm = 0; tm < 2; tm++)
                        #pragma unroll
                        for (int hlf = 0; hlf < 2; hlf++) {
                            const int tn = g * 2 + hlf;
                            MMA16816F(acc[tm][tn], Ah[tm], Bh[hlf*2], Bh[hlf*2+1]);
                            MMA16816F(acc[tm][tn], Al[tm], Bh[hlf*2], Bh[hlf*2+1]);
                        }
                }
            }
            bsel ^= 1;
        }

        // Epilogue: bias + exact GELU + q-weighted fold of the d-pair into qg.
        const int d0 = 2 * p, d1 = d0 + 1;
        #pragma unroll
        for (int tm = 0; tm < 2; tm++) {
            const int r0 = wm * 32 + tm * 16 + (lane >> 2);
            const int r1 = r0 + 8;
            const float q00 = __ldg(&g_Q[(size_t)(tok0 + r0) * EMB + h * 64 + d0]);
            const float q01 = __ldg(&g_Q[(size_t)(tok0 + r0) * EMB + h * 64 + d1]);
            const float q10 = __ldg(&g_Q[(size_t)(tok0 + r1) * EMB + h * 64 + d0]);
            const float q11 = __ldg(&g_Q[(size_t)(tok0 + r1) * EMB + h * 64 + d1]);
            #pragma unroll
            for (int eg = 0; eg < 2; eg++)
                #pragma unroll
                for (int hlf = 0; hlf < 2; hlf++) {
                    const int tnA = eg * 2 + hlf;       // d0 tile
                    const int tnB = tnA + 4;            // d1 tile
                    const int e = wn * 32 + eg * 16 + hlf * 8 + (lane & 3) * 2;
                    const float bA0 = __ldg(&bg[(size_t)h * 4096 + d0 * 64 + e]);
                    const float bA1 = __ldg(&bg[(size_t)h * 4096 + d0 * 64 + e + 1]);
                    const float bB0 = __ldg(&bg[(size_t)h * 4096 + d1 * 64 + e]);
                    const float bB1 = __ldg(&bg[(size_t)h * 4096 + d1 * 64 + e + 1]);
                    float sA0 = acc[tm][tnA][0] + bA0, sA1 = acc[tm][tnA][1] + bA1;
                    float sA2 = acc[tm][tnA][2] + bA0, sA3 = acc[tm][tnA][3] + bA1;
                    float sB0 = acc[tm][tnB][0] + bB0, sB1 = acc[tm][tnB][1] + bB1;
                    float sB2 = acc[tm][tnB][2] + bB0, sB3 = acc[tm][tnB][3] + bB1;
                    float gA0 = 0.5f * sA0 * (1.0f + erff(sA0 * kgelu));
                    float gA1 = 0.5f * sA1 * (1.0f + erff(sA1 * kgelu));
                    float gA2 = 0.5f * sA2 * (1.0f + erff(sA2 * kgelu));
                    float gA3 = 0.5f * sA3 * (1.0f + erff(sA3 * kgelu));
                    float gB0 = 0.5f * sB0 * (1.0f + erff(sB0 * kgelu));
                    float gB1 = 0.5f * sB1 * (1.0f + erff(sB1 * kgelu));
                    float gB2 = 0.5f * sB2 * (1.0f + erff(sB2 * kgelu));
                    float gB3 = 0.5f * sB3 * (1.0f + erff(sB3 * kgelu));
                    float2* p0 = (float2*)&qgs[r0 * 66 + e];
                    float2* p1 = (float2*)&qgs[r1 * 66 + e];
                    float2 v0 = *p0, v1 = *p1;
                    v0.x += q00 * gA0 + q01 * gB0;
                    v0.y += q00 * gA1 + q01 * gB1;
                    v1.x += q10 * gA2 + q11 * gB2;
                    v1.y += q10 * gA3 + q11 * gB3;
                    *p0 = v0; *p1 = v1;
                }
        }
    }

    // Final store: each (row, e) slot owned by this thread.
    #pragma unroll
    for (int tm = 0; tm < 2; tm++)
        #pragma unroll
        for (int rh = 0; rh < 2; rh++) {
            const int row = wm * 32 + tm * 16 + rh * 8 + (lane >> 2);
            #pragma unroll
            for (int eg = 0; eg < 2; eg++)
                #pragma unroll
                for (int hlf = 0; hlf < 2; hlf++) {
                    const int e = wn * 32 + eg * 16 + hlf * 8 + (lane & 3) * 2;
                    float2 v = *(float2*)&qgs[row * 66 + e];
                    *(float2*)&g_QG[(size_t)(tok0 + row) * EMB + h * 64 + e] = v;
                }
        }
}

// ---------------------------------------------------------------------------
// Kernel 3: flash-style attention (unchanged)
// ---------------------------------------------------------------------------
__global__ __launch_bounds__(128) void attn_kernel(float* __restrict__ out)
{
    __shared__ float Ks[64 * 68];
    __shared__ float Vs[64 * 68];

    const int bh  = blockIdx.y;
    const int b   = bh >> 3;
    const int h   = bh & 7;
    const int tid = threadIdx.x;
    const int n   = blockIdx.x * 128 + tid;
    const size_t rowq = (size_t)(b * SEQ + n) * EMB + h * 64;

    float4 qgr[16], outr[16];
    #pragma unroll
    for (int i = 0; i < 16; i++) {
        qgr[i]  = *(const float4*)&g_QG[rowq + i * 4];
        outr[i] = make_float4(0.f, 0.f, 0.f, 0.f);
    }
    float m = -INFINITY, l = 0.f;

    for (int kb = 0; kb < 16; kb++) {
        __syncthreads();
        #pragma unroll
        for (int it = 0; it < 8; it++) {
            int idx = tid + it * 128;
            int r   = idx >> 4;
            int c4  = (idx & 15) << 2;
            size_t g = (size_t)(b * SEQ + kb * 64 + r) * EMB + h * 64 + c4;
            *(float4*)&Ks[r * 68 + c4] = *(const float4*)&g_K[g];
            *(float4*)&Vs[r * 68 + c4] = *(const float4*)&g_V[g];
        }
        __syncthreads();

        #pragma unroll 1
        for (int j0 = 0; j0 < 64; j0 += 8) {
            float s[8];
            #pragma unroll
            for (int jj = 0; jj < 8; jj++) {
                const float* kr = &Ks[(j0 + jj) * 68];
                float a = 0.f;
                #pragma unroll
                for (int e = 0; e < 16; e++) {
                    float4 kv = *(const float4*)&kr[e * 4];
                    a = fmaf(qgr[e].x, kv.x, a);
                    a = fmaf(qgr[e].y, kv.y, a);
                    a = fmaf(qgr[e].z, kv.z, a);
                    a = fmaf(qgr[e].w, kv.w, a);
                }
                s[jj] = a;
            }
            float cmax = s[0];
            #pragma unroll
            for (int jj = 1; jj < 8; jj++) cmax = fmaxf(cmax, s[jj]);
            float mnew = fmaxf(m, cmax);
            float corr = __expf(m - mnew);
            l *= corr;
            #pragma unroll
            for (int i = 0; i < 16; i++) {
                outr[i].x *= corr; outr[i].y *= corr;
                outr[i].z *= corr; outr[i].w *= corr;
            }
            #pragma unroll
            for (int jj = 0; jj < 8; jj++) {
                float p = __expf(s[jj] - mnew);
                l += p;
                const float* vr = &Vs[(j0 + jj) * 68];
                #pragma unroll
                for (int i = 0; i < 16; i++) {
                    float4 vv = *(const float4*)&vr[i * 4];
                    outr[i].x = fmaf(p, vv.x, outr[i].x);
                    outr[i].y = fmaf(p, vv.y, outr[i].y);
                    outr[i].z = fmaf(p, vv.z, outr[i].z);
                    outr[i].w = fmaf(p, vv.w, outr[i].w);
                }
            }
            m = mnew;
        }
    }

    const float inv = 1.0f / l;
    #pragma unroll
    for (int i = 0; i < 16; i++) {
        float4 o = make_float4(outr[i].x * inv, outr[i].y * inv,
                               outr[i].z * inv, outr[i].w * inv);
        *(float4*)&out[rowq + i * 4] = o;
    }
}

// ---------------------------------------------------------------------------
extern "C" void kernel_launch(void* const* d_in, const int* in_sizes, int n_in,
                              void* d_out, int out_size)
{
    const float* x  = (const float*)d_in[0];
    const float* Wq = (const float*)d_in[1];
    const float* bq = (const float*)d_in[2];
    const float* Wk = (const float*)d_in[3];
    const float* bk = (const float*)d_in[4];
    const float* Wv = (const float*)d_in[5];
    const float* bv = (const float*)d_in[6];
    const float* Wg = (const float*)d_in[7];
    const float* bg = (const float*)d_in[8];
    float* out = (float*)d_out;

    __half *xhi, *xlo, *wh;
    cudaGetSymbolAddress((void**)&xhi, g_x_h16);
    cudaGetSymbolAddress((void**)&xlo, g_x_l16);
    cudaGetSymbolAddress((void**)&wh,  g_Wg_h16);

    {   // split x into fp16 hi/lo
        int n4 = TOK * EMB / 4;
        split2_fp16_kernel<<<(n4 + 255) / 256, 256>>>(x, xhi, xlo, n4);
    }
    {   // cast Wg to fp16 (K-major [K, N])
        int n4 = EMB * WGN / 4;
        cast_fp16_kernel<<<(n4 + 255) / 256, 256>>>(Wg, wh, n4);
    }

    dim3 g1(TOK / 64, EMB / 64, 3);
    qkv_kernel<<<g1, 256>>>(x, Wq, bq, Wk, bk, Wv, bv);

    cudaFuncSetAttribute(qg_mma_kernel, cudaFuncAttributeMaxDynamicSharedMemorySize, QG_SMEM);
    dim3 g2(TOK / 128, HEADS);
    qg_mma_kernel<<<g2, 256, QG_SMEM>>>(bg);

    dim3 g3(SEQ / 128, BATCH * HEADS);
    attn_kernel<<<g3, 128>>>(out);
}